// round 15
// baseline (speedup 1.0000x reference)
#include <cuda_runtime.h>
#include <cuda_fp16.h>
#include <math.h>
#include <stdint.h>

// ---------------- problem constants ----------------
#define BSZ   32
#define DMODEL 512
#define SEQL  128
#define NTOK  (BSZ*SEQL)     // 4096
#define NHEAD 8
#define HID   2048
#define NLAYER 8

// ---------------- scratch ----------------
__device__ float g_p  [2*BSZ*DMODEL*64];
__device__ float g_hpp[2*BSZ*DMODEL*64];
__device__ float g_M  [4*BSZ*8*64];
__device__ float g_x  [NTOK*DMODEL];
__device__ float g_ln [NTOK*DMODEL];
__device__ float g_lpartc[36*64];
__device__ float g_lpartq[36];
__device__ uint32_t g_lnh[NTOK*DMODEL/2];
__device__ uint32_t g_qh [NTOK*DMODEL/2];
__device__ uint32_t g_kh [NTOK*DMODEL/2];
__device__ uint32_t g_vh [NTOK*DMODEL/2];
__device__ uint32_t g_oh [NTOK*DMODEL/2];
__device__ uint32_t g_hh [NTOK*HID/2];
__device__ uint32_t g_wq[NLAYER*DMODEL/2*DMODEL];
__device__ uint32_t g_wk[NLAYER*DMODEL/2*DMODEL];
__device__ uint32_t g_wv[NLAYER*DMODEL/2*DMODEL];
__device__ uint32_t g_wo[NLAYER*DMODEL/2*DMODEL];
__device__ uint32_t g_w1[NLAYER*DMODEL/2*HID];
__device__ uint32_t g_w2[NLAYER*HID/2*DMODEL];

__constant__ float COS8[8] = {1.f,-0.70710678118654752f,0.f,0.70710678118654752f,
                              -1.f,0.70710678118654752f,0.f,-0.70710678118654752f};
__constant__ float SIN8[8] = {0.f,0.70710678118654752f,-1.f,0.70710678118654752f,
                              0.f,-0.70710678118654752f,1.f,-0.70710678118654752f};

// ---------------- helpers ----------------
__device__ __forceinline__ uint32_t pkh2(float a, float b) {
    __half2 h = __floats2half2_rn(a, b);
    return *reinterpret_cast<uint32_t*>(&h);
}
__device__ __forceinline__ void mma_f16(float* c, uint32_t a0, uint32_t a1,
                                        uint32_t a2, uint32_t a3,
                                        uint32_t b0, uint32_t b1) {
    asm volatile(
        "mma.sync.aligned.m16n8k16.row.col.f32.f16.f16.f32 "
        "{%0,%1,%2,%3},{%4,%5,%6,%7},{%8,%9},{%0,%1,%2,%3};"
        : "+f"(c[0]), "+f"(c[1]), "+f"(c[2]), "+f"(c[3])
        : "r"(a0), "r"(a1), "r"(a2), "r"(a3), "r"(b0), "r"(b1));
}
__device__ __forceinline__ uint32_t smem_u32_of(const void* p) {
    uint32_t a;
    asm("{ .reg .u64 t; cvta.to.shared.u64 t, %1; cvt.u32.u64 %0, t; }" : "=r"(a) : "l"(p));
    return a;
}

// ---------------- fused weight packing ----------
#define QKV_U4 (NLAYER*256*128)
#define W1_U4  (NLAYER*256*512)
#define PACK_TOTAL (4*QKV_U4 + 2*W1_U4)
__global__ void pack_all(
    const float* __restrict__ Wq, const float* __restrict__ Wk,
    const float* __restrict__ Wv, const float* __restrict__ Wo,
    const float* __restrict__ W1, const float* __restrict__ W2,
    uint32_t* __restrict__ oq, uint32_t* __restrict__ ok,
    uint32_t* __restrict__ ov, uint32_t* __restrict__ oo,
    uint32_t* __restrict__ o1, uint32_t* __restrict__ o2)
{
    int i = blockIdx.x*256 + threadIdx.x;
    if (i >= PACK_TOTAL) return;
    const float* W; uint32_t* out; int local, N;
    if (i < 4*QKV_U4) {
        int sel = i >> 18;
        local = i & (QKV_U4 - 1);
        N = 512;
        W = (sel == 0) ? Wq : (sel == 1) ? Wk : (sel == 2) ? Wv : Wo;
        out = (sel == 0) ? oq : (sel == 1) ? ok : (sel == 2) ? ov : oo;
    } else if (i < 4*QKV_U4 + W1_U4) {
        local = i - 4*QKV_U4; N = 2048; W = W1; out = o1;
    } else {
        local = i - 4*QKV_U4 - W1_U4; N = 512; W = W2; out = o2;
    }
    int nw4 = N >> 2;
    int k2 = local / nw4;
    int n  = (local - k2*nw4)*4;
    float4 r0 = *(const float4*)(W + (size_t)(2*k2)*N + n);
    float4 r1 = *(const float4*)(W + (size_t)(2*k2+1)*N + n);
    ((uint4*)out)[local] = make_uint4(pkh2(r0.x, r1.x), pkh2(r0.y, r1.y),
                                      pkh2(r0.z, r1.z), pkh2(r0.w, r1.w));
}

// ---------------- 1) avgpool 4x4 + single-bin highpass ----------
__global__ void pool_hp_kernel(const float* __restrict__ rgb, const float* __restrict__ ir) {
    __shared__ float sp[64];
    __shared__ float red[4];
    int c = blockIdx.x, b = blockIdx.y, src = blockIdx.z;
    int tid = threadIdx.x;
    const float* in = (src == 0 ? rgb : ir) + ((size_t)(b*DMODEL + c))*1024;
    float4 v = ((const float4*)in)[tid];
    float t = v.x + v.y + v.z + v.w;
    t += __shfl_xor_sync(0xffffffffu, t, 8);
    t += __shfl_xor_sync(0xffffffffu, t, 16);
    int lane = tid & 31, w = tid >> 5;
    if (lane < 8) sp[w*8 + lane] = t*(1.f/16.f);
    __syncthreads();
    size_t base = ((size_t)((src*BSZ + b)*DMODEL + c))*64;
    float x = 0.f, ct = 0.f, st = 0.f;
    if (tid < 64) {
        x = sp[tid];
        g_p[base + tid] = x;
        int idx = (3*((tid>>3) + (tid&7))) & 7;
        ct = COS8[idx]; st = SIN8[idx];
    }
    float xc = x*ct, xs = x*st;
    if (tid < 64) {
        #pragma unroll
        for (int off = 16; off; off >>= 1) {
            xc += __shfl_down_sync(0xffffffffu, xc, off);
            xs += __shfl_down_sync(0xffffffffu, xs, off);
        }
        if ((tid&31) == 0) { red[(tid>>5)*2] = xc; red[(tid>>5)*2+1] = xs; }
    }
    __syncthreads();
    if (tid < 64) {
        float Fr = red[0] + red[2];
        float Fi = -(red[1] + red[3]);
        float hp = x - (Fr*ct - Fi*st)*(1.f/64.f);
        g_hpp[base + tid] = hp * x;
    }
}

// ---------------- 2) conv1 (512->8) + sigmoid, partial-sum form ------------
__global__ void conv1_kernel(const float* __restrict__ w) {
    __shared__ float sw[4096];
    __shared__ float part[8][8][65];
    int b = blockIdx.x, v = blockIdx.y;
    int tid = threadIdx.x;
    for (int i = tid; i < 4096; i += 512) sw[i] = w[i];
    const float* X = (v < 2 ? g_p : g_hpp) + ((size_t)(((v&1)*BSZ + b)*DMODEL))*64;
    __syncthreads();
    int p = tid >> 6, s = tid & 63;
    float acc[8] = {};
    const float* Xp = X + (size_t)(p*64)*64 + s;
    #pragma unroll 8
    for (int j = 0; j < 64; j++) {
        float xv = Xp[(size_t)j*64];
        #pragma unroll
        for (int o = 0; o < 8; o++) acc[o] += sw[o*512 + p*64 + j] * xv;
    }
    #pragma unroll
    for (int o = 0; o < 8; o++) part[p][o][s] = acc[o];
    __syncthreads();
    int o = tid >> 6;
    float sum = 0.f;
    #pragma unroll
    for (int pp = 0; pp < 8; pp++) sum += part[pp][o][s];
    g_M[((size_t)(v*BSZ + b)*8 + o)*64 + s] = 1.f/(1.f + __expf(-sum));
}

// ---------------- 3) pattern loss: two-phase -------------------------------
__global__ void loss_partA() {
    __shared__ float sc[4][64];
    __shared__ float ssq[8];
    int blk = blockIdx.x, tid = threadIdx.x;
    int col = tid & 63, rg = tid >> 6;
    float s = 0.f, sq = 0.f;
    #pragma unroll
    for (int j = rg; j < 16; j += 4) {
        int vr = blk*16 + j;
        int row = (vr < 544) ? vr : vr + 224;
        float m = g_M[(size_t)row*64 + col];
        s += m; sq += m*m;
    }
    sc[rg][col] = s;
    #pragma unroll
    for (int off = 16; off; off >>= 1) sq += __shfl_down_sync(0xffffffffu, sq, off);
    if ((tid&31) == 0) ssq[tid>>5] = sq;
    __syncthreads();
    if (tid < 64)
        g_lpartc[blk*64 + tid] = sc[0][tid] + sc[1][tid] + sc[2][tid] + sc[3][tid];
    if (tid == 0) {
        float q = 0.f;
        #pragma unroll
        for (int wi = 0; wi < 8; wi++) q += ssq[wi];
        g_lpartq[blk] = q;
    }
}
__global__ void loss_partB(float* __restrict__ out_loss) {
    __shared__ float sred[2];
    int tid = threadIdx.x;
    float cs = 0.f;
    for (int b = 0; b < 36; b++) cs += g_lpartc[b*64 + tid];
    float v = cs*cs;
    #pragma unroll
    for (int off = 16; off; off >>= 1) v += __shfl_down_sync(0xffffffffu, v, off);
    if ((tid&31) == 0) sred[tid>>5] = v;
    __syncthreads();
    if (tid == 0) {
        float ss = sred[0] + sred[1];
        float sq = 0.f;
        for (int b = 0; b < 36; b++) sq += g_lpartq[b];
        out_loss[0] = (ss - sq)*0.5f/(576.f*575.f);
    }
}

// ---------------- 4) tokens -------------------------------------------------
__global__ void buildx_kernel(const float* __restrict__ pos, const float* __restrict__ c2w) {
    __shared__ float sw[4096];
    __shared__ float sm[16][8];
    int bt = blockIdx.x, b = blockIdx.y;
    int d = threadIdx.x;
    for (int i = d; i < 4096; i += 512) sw[i] = c2w[i];
    int which = (bt*16) >> 6;
    if (d < 128) {
        int i = d >> 3, o = d & 7;
        int t = bt*16 + i, s = t & 63;
        sm[i][o] = g_M[((size_t)(which*BSZ + b)*8 + o)*64 + s];
    }
    __syncthreads();
    float w0 = sw[d*8], w1 = sw[d*8+1], w2 = sw[d*8+2], w3 = sw[d*8+3];
    float w4 = sw[d*8+4], w5 = sw[d*8+5], w6 = sw[d*8+6], w7 = sw[d*8+7];
    #pragma unroll
    for (int i = 0; i < 16; i++) {
        int t = bt*16 + i, s = t & 63;
        float acc = w0*sm[i][0] + w1*sm[i][1] + w2*sm[i][2] + w3*sm[i][3]
                  + w4*sm[i][4] + w5*sm[i][5] + w6*sm[i][6] + w7*sm[i][7];
        float p = g_p[((size_t)((which*BSZ + b)*DMODEL + d))*64 + s];
        g_x[(size_t)(b*SEQL + t)*DMODEL + d] = pos[t*DMODEL + d] + acc*p;
    }
}

// ---------------- LayerNorm: warp-per-row ----------------------------------
template<bool PACK>
__global__ void ln_kernel(const float* __restrict__ x, void* __restrict__ y,
                          const float* __restrict__ w, const float* __restrict__ bsh) {
    int row = blockIdx.x*8 + (threadIdx.x >> 5);
    int lane = threadIdx.x & 31;
    const float4* xr = (const float4*)(x + (size_t)row*512);
    float4 v[4];
    float sum = 0.f, sq = 0.f;
    #pragma unroll
    for (int i = 0; i < 4; i++) {
        v[i] = xr[lane + 32*i];
        sum += v[i].x + v[i].y + v[i].z + v[i].w;
        sq  += v[i].x*v[i].x + v[i].y*v[i].y + v[i].z*v[i].z + v[i].w*v[i].w;
    }
    #pragma unroll
    for (int off = 16; off; off >>= 1) {
        sum += __shfl_xor_sync(0xffffffffu, sum, off);
        sq  += __shfl_xor_sync(0xffffffffu, sq,  off);
    }
    float mean = sum*(1.f/512.f);
    float inv = rsqrtf(sq*(1.f/512.f) - mean*mean + 1e-5f);
    #pragma unroll
    for (int i = 0; i < 4; i++) {
        int idx = lane + 32*i;
        float4 wv = ((const float4*)w)[idx];
        float4 bv = ((const float4*)bsh)[idx];
        float4 o;
        o.x = (v[i].x-mean)*inv*wv.x + bv.x;
        o.y = (v[i].y-mean)*inv*wv.y + bv.y;
        o.z = (v[i].z-mean)*inv*wv.z + bv.z;
        o.w = (v[i].w-mean)*inv*wv.w + bv.w;
        if (PACK) {
            ((uint2*)((uint32_t*)y + (size_t)row*256))[idx] =
                make_uint2(pkh2(o.x, o.y), pkh2(o.z, o.w));
        } else {
            ((float4*)((float*)y + (size_t)row*512))[idx] = o;
        }
    }
}

// ================= fp16 GEMM core: cp.async 4-stage, BK=32 ================
#define GEMM_AW 1280
#define GEMM_BW 2176
#define GEMM_STW (GEMM_AW + GEMM_BW)
#define GEMM_STB (GEMM_STW*4)
#define GEMM_SMEM (4*GEMM_STB)

template<int ACT, bool OUTHALF>
__device__ __forceinline__ void gemm_core(
    const uint32_t* __restrict__ A, const uint32_t* __restrict__ B,
    const float* __restrict__ bias, const float* __restrict__ resid,
    void* __restrict__ Cv, int N, int K, int bm, int bn, char* smem)
{
    uint32_t sb = smem_u32_of(smem);
    int tid = threadIdx.x;
    int warp = tid>>5, lane = tid&31;
    int wm = (warp&1)*32, wn = (warp>>1)*64;
    int lr = lane>>2, lc = lane&3;
    int K2 = K >> 1;

    float acc[2][8][4] = {};

    auto issue = [&](int stg, int kt) {
        uint32_t ab = sb + (uint32_t)stg*GEMM_STB;
        uint32_t bb = ab + GEMM_AW*4;
        int k0 = kt << 4;
        #pragma unroll
        for (int i = 0; i < 2; i++) {
            int c = tid + i*128;
            int row = c>>2, pos = (c&3)*4;
            const uint32_t* sa = A + (size_t)(bm+row)*K2 + k0 + pos;
            uint32_t da = ab + (uint32_t)(row*20 + pos)*4;
            asm volatile("cp.async.cg.shared.global [%0], [%1], 16;"
                         :: "r"(da), "l"(sa) : "memory");
        }
        #pragma unroll
        for (int i = 0; i < 4; i++) {
            int c = tid + i*128;
            int row = c>>5, pos = (c&31)*4;
            const uint32_t* sv = B + (size_t)(k0 + row)*N + bn + pos;
            uint32_t db = bb + (uint32_t)(row*136 + pos)*4;
            asm volatile("cp.async.cg.shared.global [%0], [%1], 16;"
                         :: "r"(db), "l"(sv) : "memory");
        }
        asm volatile("cp.async.commit_group;" ::: "memory");
    };

    int KT = K >> 5;
    issue(0, 0); issue(1, 1); issue(2, 2);

    for (int kt = 0; kt < KT; kt++) {
        asm volatile("cp.async.wait_group 2;" ::: "memory");
        __syncthreads();
        int nk = kt + 3;
        if (nk < KT) issue(nk & 3, nk);
        else asm volatile("cp.async.commit_group;" ::: "memory");

        const uint32_t* As = (const uint32_t*)(smem + (size_t)(kt&3)*GEMM_STB);
        const uint32_t* Bs = As + GEMM_AW;
        #pragma unroll
        for (int st = 0; st < 2; st++) {
            int cw = st*8 + lc;
            uint32_t a[2][4], b[8][2];
            #pragma unroll
            for (int mt = 0; mt < 2; mt++) {
                int r0 = wm + mt*16 + lr;
                a[mt][0] = As[r0*20 + cw];
                a[mt][1] = As[(r0+8)*20 + cw];
                a[mt][2] = As[r0*20 + cw + 4];
                a[mt][3] = As[(r0+8)*20 + cw + 4];
            }
            #pragma unroll
            for (int nt = 0; nt < 8; nt++) {
                int cn = wn + nt*8 + lr;
                b[nt][0] = Bs[cw*136 + cn];
                b[nt][1] = Bs[(cw+4)*136 + cn];
            }
            #pragma unroll
            for (int mt = 0; mt < 2; mt++)
                #pragma unroll
                for (int nt = 0; nt < 8; nt++)
                    mma_f16(acc[mt][nt], a[mt][0], a[mt][1], a[mt][2], a[mt][3],
                            b[nt][0], b[nt][1]);
        }
    }

    #pragma unroll
    for (int mt = 0; mt < 2; mt++) {
        int row0 = bm + wm + mt*16 + lr;
        #pragma unroll
        for (int nt = 0; nt < 8; nt++) {
            int col = bn + wn + nt*8 + 2*lc;
            float2 bb = *(const float2*)(bias + col);
            float v0 = acc[mt][nt][0] + bb.x, v1 = acc[mt][nt][1] + bb.y;
            float v2 = acc[mt][nt][2] + bb.x, v3 = acc[mt][nt][3] + bb.y;
            if (ACT == 1) {
                v0 *= normcdff(v0); v1 *= normcdff(v1);
                v2 *= normcdff(v2); v3 *= normcdff(v3);
            }
            if (OUTHALF) {
                uint32_t* C16 = (uint32_t*)Cv;
                int Nw = N >> 1;
                C16[(size_t)row0*Nw + (col>>1)]     = pkh2(v0, v1);
                C16[(size_t)(row0+8)*Nw + (col>>1)] = pkh2(v2, v3);
            } else {
                float* C = (float*)Cv;
                size_t o0 = (size_t)row0*N + col;
                size_t o1 = (size_t)(row0+8)*N + col;
                if (ACT == 2) {
                    float2 r0 = *(const float2*)(resid + o0);
                    float2 r1 = *(const float2*)(resid + o1);
                    v0 += r0.x; v1 += r0.y; v2 += r1.x; v3 += r1.y;
                }
                *(float2*)(C + o0) = make_float2(v0, v1);
                *(float2*)(C + o1) = make_float2(v2, v3);
            }
        }
    }
}

template<int ACT, bool OUTHALF>
__global__ void __launch_bounds__(128, 3) gemm_kernel(
    const uint32_t* __restrict__ A, const uint32_t* __restrict__ B,
    const float* __restrict__ bias, const float* __restrict__ resid,
    void* __restrict__ C, int N, int K)
{
    extern __shared__ char smem[];
    gemm_core<ACT, OUTHALF>(A, B, bias, resid, C, N, K,
                            blockIdx.y*64, blockIdx.x*128, smem);
}

// fused QKV: grid (12, 64)
__global__ void __launch_bounds__(128, 3) gemm_qkv_kernel(
    const uint32_t* __restrict__ A,
    const uint32_t* __restrict__ wq, const uint32_t* __restrict__ wk,
    const uint32_t* __restrict__ wv,
    const float* __restrict__ bq, const float* __restrict__ bk,
    const float* __restrict__ bv,
    uint32_t* __restrict__ q, uint32_t* __restrict__ k, uint32_t* __restrict__ v)
{
    extern __shared__ char smem[];
    int sel = blockIdx.x >> 2;
    int bn = (blockIdx.x & 3)*128;
    const uint32_t* B = (sel == 0) ? wq : (sel == 1) ? wk : wv;
    const float* bias = (sel == 0) ? bq : (sel == 1) ? bk : bv;
    uint32_t* C = (sel == 0) ? q : (sel == 1) ? k : v;
    gemm_core<0, true>(A, B, bias, nullptr, C, 512, 512, blockIdx.y*64, bn, smem);
}

// ---------------- fused fp16 attention per (b,h,half) ----------------------
// grid (256,2), 128 thr. smem: V[64*72] | Q[64*36] | K[128*36]; P alias Q+K head.
#define ATTN_SMEM ((64*72 + 64*36 + 128*36)*4)   // 45056 B
__global__ void __launch_bounds__(128, 2) attn_kernel() {
    extern __shared__ uint32_t smw[];
    uint32_t* Vs = smw;
    uint32_t* Qs = smw + 64*72;
    uint32_t* Ks = Qs + 64*36;
    uint32_t* Ps = Qs;   // [64][68] = 4352 <= 64*36+128*36 = 6912 words

    int bh = blockIdx.x, b = bh >> 3, h = bh & 7;
    int qbase = blockIdx.y*64;
    int tid = threadIdx.x, warp = tid>>5, lane = tid&31;
    int lr = lane>>2, lc = lane&3;
    const uint32_t* qp = g_qh + (size_t)(b*SEQL)*256 + h*32;
    const uint32_t* kp = g_kh + (size_t)(b*SEQL)*256 + h*32;
    const uint32_t* vp = g_vh + (size_t)(b*SEQL)*256 + h*32;

    #pragma unroll
    for (int i = 0; i < 4; i++) {          // Q: 64 rows x 8 chunks = 512 tasks
        int idx = tid + i*128;
        int s = idx >> 3, pos = (idx & 7)*4;
        *(uint4*)&Qs[s*36 + pos] = *(const uint4*)(qp + (size_t)(qbase + s)*256 + pos);
    }
    #pragma unroll
    for (int i = 0; i < 8; i++) {          // K: 128 rows x 8 chunks = 1024 tasks
        int idx = tid + i*128;
        int s = idx >> 3, pos = (idx & 7)*4;
        *(uint4*)&Ks[s*36 + pos] = *(const uint4*)(kp + (size_t)s*256 + pos);
    }
    #pragma unroll
    for (int i = 0; i < 16; i++) {         // V transpose: 2048 tasks
        int t = tid + i*128;
        int sp = t >> 5, dp = t & 31;
        uint32_t w0 = vp[(size_t)(2*sp)*256 + dp];
        uint32_t w1 = vp[(size_t)(2*sp+1)*256 + dp];
        Vs[sp*72 + 2*dp]     = __byte_perm(w0, w1, 0x5410);
        Vs[sp*72 + 2*dp + 1] = __byte_perm(w0, w1, 0x7632);
    }
    __syncthreads();

    int qr = warp*16 + lr;   // local q-row 0..63
    float accs[16][4] = {};
    #pragma unroll
    for (int st = 0; st < 4; st++) {
        int cw = st*8 + lc;
        uint32_t a0 = Qs[qr*36 + cw],     a1 = Qs[(qr+8)*36 + cw];
        uint32_t a2 = Qs[qr*36 + cw + 4], a3 = Qs[(qr+8)*36 + cw + 4];
        #pragma unroll
        for (int nt = 0; nt < 16; nt++) {
            int kn = nt*8 + lr;
            uint32_t b0 = Ks[kn*36 + cw];
            uint32_t b1 = Ks[kn*36 + cw + 4];
            mma_f16(accs[nt], a0, a1, a2, a3, b0, b1);
        }
    }
    float m0 = -1e30f, m1 = -1e30f;
    #pragma unroll
    for (int nt = 0; nt < 16; nt++) {
        #pragma unroll
        for (int j = 0; j < 4; j++) accs[nt][j] *= 0.125f;
        m0 = fmaxf(m0, fmaxf(accs[nt][0], accs[nt][1]));
        m1 = fmaxf(m1, fmaxf(accs[nt][2], accs[nt][3]));
    }
    m0 = fmaxf(m0, __shfl_xor_sync(0xffffffffu, m0, 1));
    m0 = fmaxf(m0, __shfl_xor_sync(0xffffffffu, m0, 2));
    m1 = fmaxf(m1, __shfl_xor_sync(0xffffffffu, m1, 1));
    m1 = fmaxf(m1, __shfl_xor_sync(0xffffffffu, m1, 2));
    float s0 = 0.f, s1 = 0.f;
    #pragma unroll
    for (int nt = 0; nt < 16; nt++) {
        accs[nt][0] = __expf(accs[nt][0] - m0);
        accs[nt][1] = __expf(accs[nt][1] - m0);
        accs[nt][2] = __expf(accs[nt][2] - m1);
        accs[nt][3] = __expf(accs[nt][3] - m1);
        s0 += accs[nt][0] + accs[nt][1];
        s1 += accs[nt][2] + accs[nt][3];
    }
    s0 += __shfl_xor_sync(0xffffffffu, s0, 1);
    s0 += __shfl_xor_sync(0xffffffffu, s0, 2);
    s1 += __shfl_xor_sync(0xffffffffu, s1, 1);
    s1 += __shfl_xor_sync(0xffffffffu, s1, 2);
    float i0 = 1.f/s0, i1 = 1.f/s1;

    __syncthreads();   // all warps done with Qs before P overwrites
    #pragma unroll
    for (int nt = 0; nt < 16; nt++) {
        int wdi = nt*4 + lc;
        Ps[qr*68 + wdi]     = pkh2(accs[nt][0]*i0, accs[nt][1]*i0);
        Ps[(qr+8)*68 + wdi] = pkh2(accs[nt][2]*i1, accs[nt][3]*i1);
    }
    __syncthreads();

    float acco[8][4] = {};
    #pragma unroll
    for (int kk = 0; kk < 8; kk++) {
        int cw = kk*8 + lc;
        uint32_t a0 = Ps[qr*68 + cw],     a1 = Ps[(qr+8)*68 + cw];
        uint32_t a2 = Ps[qr*68 + cw + 4], a3 = Ps[(qr+8)*68 + cw + 4];
        #pragma unroll
        for (int nt = 0; nt < 8; nt++) {
            int dn = nt*8 + lr;
            uint32_t b0 = Vs[cw*72 + dn];
            uint32_t b1 = Vs[(cw+4)*72 + dn];
            mma_f16(acco[nt], a0, a1, a2, a3, b0, b1);
        }
    }
    uint32_t* op = g_oh + (size_t)(b*SEQL)*256 + h*32;
    #pragma unroll
    for (int nt = 0; nt < 8; nt++) {
        int wdi = nt*4 + lc;
        op[(size_t)(qbase + qr)*256 + wdi]     = pkh2(acco[nt][0], acco[nt][1]);
        op[(size_t)(qbase + qr + 8)*256 + wdi] = pkh2(acco[nt][2], acco[nt][3]);
    }
}

// ---------------- bilinear upsample 8x8 -> 32x32 ----------------------------
__global__ void upsample_kernel(float* __restrict__ out) {
    __shared__ float g[64];
    int d = blockIdx.x, b = blockIdx.y, which = blockIdx.z;
    int tid = threadIdx.x;
    if (tid < 64)
        g[tid] = g_ln[(size_t)(b*SEQL + which*64 + tid)*512 + d];
    __syncthreads();
    float* op = out + (size_t)which*(BSZ*512*1024) + ((size_t)(b*512 + d))*1024;
    #pragma unroll
    for (int r = 0; r < 4; r++) {
        int pix = tid + r*256;
        int oy = pix >> 5, ox = pix & 31;
        float cy = (oy + 0.5f)*0.25f - 0.5f;
        float cx = (ox + 0.5f)*0.25f - 0.5f;
        int y0 = (int)floorf(cy); float wy = cy - y0;
        int x0 = (int)floorf(cx); float wx = cx - x0;
        int y1 = min(y0+1, 7); y0 = max(y0, 0);
        int x1 = min(x0+1, 7); x0 = max(x0, 0);
        float v00 = g[y0*8+x0], v01 = g[y0*8+x1], v10 = g[y1*8+x0], v11 = g[y1*8+x1];
        op[pix] = (1.f-wy)*((1.f-wx)*v00 + wx*v01) + wy*((1.f-wx)*v10 + wx*v11);
    }
}

// ---------------- launcher --------------------------------------------------
extern "C" void kernel_launch(void* const* d_in, const int* in_sizes, int n_in,
                              void* d_out, int out_size) {
    const float* rgb  = (const float*)d_in[0];
    const float* ir   = (const float*)d_in[1];
    const float* pos  = (const float*)d_in[2];
    const float* c1w  = (const float*)d_in[3];
    const float* c2w  = (const float*)d_in[4];
    const float* ln1w = (const float*)d_in[5];
    const float* ln1b = (const float*)d_in[6];
    const float* Wq   = (const float*)d_in[7];
    const float* bq   = (const float*)d_in[8];
    const float* Wk   = (const float*)d_in[9];
    const float* bk   = (const float*)d_in[10];
    const float* Wv   = (const float*)d_in[11];
    const float* bv   = (const float*)d_in[12];
    const float* Wo   = (const float*)d_in[13];
    const float* bo   = (const float*)d_in[14];
    const float* ln2w = (const float*)d_in[15];
    const float* ln2b = (const float*)d_in[16];
    const float* W1   = (const float*)d_in[17];
    const float* b1   = (const float*)d_in[18];
    const float* W2   = (const float*)d_in[19];
    const float* b2   = (const float*)d_in[20];
    const float* lnfw = (const float*)d_in[21];
    const float* lnfb = (const float*)d_in[22];
    float* out = (float*)d_out;

    float *p_x, *p_ln;
    uint32_t *p_lnh, *p_qh, *p_kh, *p_vh, *p_oh, *p_hh;
    uint32_t *p_wq, *p_wk, *p_wv, *p_wo, *p_w1, *p_w2;
    cudaGetSymbolAddress((void**)&p_x,   g_x);
    cudaGetSymbolAddress((void**)&p_ln,  g_ln);
    cudaGetSymbolAddress((void**)&p_lnh, g_lnh);
    cudaGetSymbolAddress((void**)&p_qh,  g_qh);
    cudaGetSymbolAddress((void**)&p_kh,  g_kh);
    cudaGetSymbolAddress((void**)&p_vh,  g_vh);
    cudaGetSymbolAddress((void**)&p_oh,  g_oh);
    cudaGetSymbolAddress((void**)&p_hh,  g_hh);
    cudaGetSymbolAddress((void**)&p_wq,  g_wq);
    cudaGetSymbolAddress((void**)&p_wk,  g_wk);
    cudaGetSymbolAddress((void**)&p_wv,  g_wv);
    cudaGetSymbolAddress((void**)&p_wo,  g_wo);
    cudaGetSymbolAddress((void**)&p_w1,  g_w1);
    cudaGetSymbolAddress((void**)&p_w2,  g_w2);

    cudaFuncSetAttribute(attn_kernel, cudaFuncAttributeMaxDynamicSharedMemorySize, ATTN_SMEM);
    cudaFuncSetAttribute(gemm_qkv_kernel, cudaFuncAttributeMaxDynamicSharedMemorySize, GEMM_SMEM);
    cudaFuncSetAttribute(gemm_kernel<2,false>, cudaFuncAttributeMaxDynamicSharedMemorySize, GEMM_SMEM);
    cudaFuncSetAttribute(gemm_kernel<1,true>, cudaFuncAttributeMaxDynamicSharedMemorySize, GEMM_SMEM);

    pack_all<<<(PACK_TOTAL+255)/256, 256>>>(Wq, Wk, Wv, Wo, W1, W2,
                                            p_wq, p_wk, p_wv, p_wo, p_w1, p_w2);

    pool_hp_kernel<<<dim3(DMODEL, BSZ, 2), 256>>>(rgb, ir);
    conv1_kernel<<<dim3(BSZ, 4), 512>>>(c1w);
    loss_partA<<<36, 256>>>();
    loss_partB<<<1, 64>>>(out + (size_t)2*BSZ*512*1024);
    buildx_kernel<<<dim3(8, BSZ), 512>>>(pos, c2w);

    dim3 gqkv(12, NTOK/64);          // 768 CTAs
    dim3 g512(4, NTOK/64);           // 256 CTAs
    dim3 g2048(16, NTOK/64);         // 1024 CTAs

    for (int l = 0; l < NLAYER; l++) {
        size_t wOff = (size_t)l*(DMODEL/2)*DMODEL;
        size_t w1Off = (size_t)l*(DMODEL/2)*HID;
        size_t w2Off = (size_t)l*(HID/2)*DMODEL;
        size_t bOff = (size_t)l*512, b1Off = (size_t)l*2048;
        ln_kernel<true><<<NTOK/8, 256>>>(p_x, p_lnh, ln1w + bOff, ln1b + bOff);
        gemm_qkv_kernel<<<gqkv, 128, GEMM_SMEM>>>(p_lnh,
            p_wq + wOff, p_wk + wOff, p_wv + wOff,
            bq + bOff, bk + bOff, bv + bOff, p_qh, p_kh, p_vh);
        attn_kernel<<<dim3(BSZ*NHEAD, 2), 128, ATTN_SMEM>>>();
        gemm_kernel<2,false><<<g512, 128, GEMM_SMEM>>>(p_oh, p_wo + wOff,
            bo + bOff, p_x, p_x, 512, 512);
        ln_kernel<true><<<NTOK/8, 256>>>(p_x, p_lnh, ln2w + bOff, ln2b + bOff);
        gemm_kernel<1,true><<<g2048, 128, GEMM_SMEM>>>(p_lnh, p_w1 + w1Off,
            b1 + b1Off, nullptr, p_hh, 2048, 512);
        gemm_kernel<2,false><<<g512, 128, GEMM_SMEM>>>(p_hh, p_w2 + w2Off,
            b2 + bOff, p_x, p_x, 512, 2048);
    }
    ln_kernel<false><<<NTOK/8, 256>>>(p_x, p_ln, lnfw, lnfb);
    upsample_kernel<<<dim3(512, BSZ, 2), 256>>>(out);
}

// round 16
// speedup vs baseline: 1.0225x; 1.0225x over previous
#include <cuda_runtime.h>
#include <cuda_fp16.h>
#include <math.h>
#include <stdint.h>

// ---------------- problem constants ----------------
#define BSZ   32
#define DMODEL 512
#define SEQL  128
#define NTOK  (BSZ*SEQL)     // 4096
#define NHEAD 8
#define HID   2048
#define NLAYER 8

// ---------------- scratch ----------------
__device__ float g_p  [2*BSZ*DMODEL*64];
__device__ float g_hpp[2*BSZ*DMODEL*64];
__device__ float g_M  [4*BSZ*8*64];
__device__ float g_x  [NTOK*DMODEL];
__device__ float g_ln [NTOK*DMODEL];
__device__ float g_lpartc[36*64];
__device__ float g_lpartq[36];
__device__ uint32_t g_lnh[NTOK*DMODEL/2];
__device__ uint32_t g_qh [NTOK*DMODEL/2];
__device__ uint32_t g_kh [NTOK*DMODEL/2];
__device__ uint32_t g_vh [NTOK*DMODEL/2];
__device__ uint32_t g_oh [NTOK*DMODEL/2];
__device__ uint32_t g_hh [NTOK*HID/2];
__device__ uint32_t g_wq[NLAYER*DMODEL/2*DMODEL];
__device__ uint32_t g_wk[NLAYER*DMODEL/2*DMODEL];
__device__ uint32_t g_wv[NLAYER*DMODEL/2*DMODEL];
__device__ uint32_t g_wo[NLAYER*DMODEL/2*DMODEL];
__device__ uint32_t g_w1[NLAYER*DMODEL/2*HID];
__device__ uint32_t g_w2[NLAYER*HID/2*DMODEL];

__constant__ float COS8[8] = {1.f,-0.70710678118654752f,0.f,0.70710678118654752f,
                              -1.f,0.70710678118654752f,0.f,-0.70710678118654752f};
__constant__ float SIN8[8] = {0.f,0.70710678118654752f,-1.f,0.70710678118654752f,
                              0.f,-0.70710678118654752f,1.f,-0.70710678118654752f};

// ---------------- helpers ----------------
__device__ __forceinline__ uint32_t pkh2(float a, float b) {
    __half2 h = __floats2half2_rn(a, b);
    return *reinterpret_cast<uint32_t*>(&h);
}
__device__ __forceinline__ void mma_f16(float* c, uint32_t a0, uint32_t a1,
                                        uint32_t a2, uint32_t a3,
                                        uint32_t b0, uint32_t b1) {
    asm volatile(
        "mma.sync.aligned.m16n8k16.row.col.f32.f16.f16.f32 "
        "{%0,%1,%2,%3},{%4,%5,%6,%7},{%8,%9},{%0,%1,%2,%3};"
        : "+f"(c[0]), "+f"(c[1]), "+f"(c[2]), "+f"(c[3])
        : "r"(a0), "r"(a1), "r"(a2), "r"(a3), "r"(b0), "r"(b1));
}
__device__ __forceinline__ uint32_t smem_u32_of(const void* p) {
    uint32_t a;
    asm("{ .reg .u64 t; cvta.to.shared.u64 t, %1; cvt.u32.u64 %0, t; }" : "=r"(a) : "l"(p));
    return a;
}

// ---------------- fused weight packing ----------
#define QKV_U4 (NLAYER*256*128)
#define W1_U4  (NLAYER*256*512)
#define PACK_TOTAL (4*QKV_U4 + 2*W1_U4)
__global__ void pack_all(
    const float* __restrict__ Wq, const float* __restrict__ Wk,
    const float* __restrict__ Wv, const float* __restrict__ Wo,
    const float* __restrict__ W1, const float* __restrict__ W2,
    uint32_t* __restrict__ oq, uint32_t* __restrict__ ok,
    uint32_t* __restrict__ ov, uint32_t* __restrict__ oo,
    uint32_t* __restrict__ o1, uint32_t* __restrict__ o2)
{
    int i = blockIdx.x*256 + threadIdx.x;
    if (i >= PACK_TOTAL) return;
    const float* W; uint32_t* out; int local, N;
    if (i < 4*QKV_U4) {
        int sel = i >> 18;
        local = i & (QKV_U4 - 1);
        N = 512;
        W = (sel == 0) ? Wq : (sel == 1) ? Wk : (sel == 2) ? Wv : Wo;
        out = (sel == 0) ? oq : (sel == 1) ? ok : (sel == 2) ? ov : oo;
    } else if (i < 4*QKV_U4 + W1_U4) {
        local = i - 4*QKV_U4; N = 2048; W = W1; out = o1;
    } else {
        local = i - 4*QKV_U4 - W1_U4; N = 512; W = W2; out = o2;
    }
    int nw4 = N >> 2;
    int k2 = local / nw4;
    int n  = (local - k2*nw4)*4;
    float4 r0 = *(const float4*)(W + (size_t)(2*k2)*N + n);
    float4 r1 = *(const float4*)(W + (size_t)(2*k2+1)*N + n);
    ((uint4*)out)[local] = make_uint4(pkh2(r0.x, r1.x), pkh2(r0.y, r1.y),
                                      pkh2(r0.z, r1.z), pkh2(r0.w, r1.w));
}

// ---------------- 1) avgpool 4x4 + single-bin highpass ----------
__global__ void pool_hp_kernel(const float* __restrict__ rgb, const float* __restrict__ ir) {
    __shared__ float sp[64];
    __shared__ float red[4];
    int c = blockIdx.x, b = blockIdx.y, src = blockIdx.z;
    int tid = threadIdx.x;
    const float* in = (src == 0 ? rgb : ir) + ((size_t)(b*DMODEL + c))*1024;
    float4 v = ((const float4*)in)[tid];
    float t = v.x + v.y + v.z + v.w;
    t += __shfl_xor_sync(0xffffffffu, t, 8);
    t += __shfl_xor_sync(0xffffffffu, t, 16);
    int lane = tid & 31, w = tid >> 5;
    if (lane < 8) sp[w*8 + lane] = t*(1.f/16.f);
    __syncthreads();
    size_t base = ((size_t)((src*BSZ + b)*DMODEL + c))*64;
    float x = 0.f, ct = 0.f, st = 0.f;
    if (tid < 64) {
        x = sp[tid];
        g_p[base + tid] = x;
        int idx = (3*((tid>>3) + (tid&7))) & 7;
        ct = COS8[idx]; st = SIN8[idx];
    }
    float xc = x*ct, xs = x*st;
    if (tid < 64) {
        #pragma unroll
        for (int off = 16; off; off >>= 1) {
            xc += __shfl_down_sync(0xffffffffu, xc, off);
            xs += __shfl_down_sync(0xffffffffu, xs, off);
        }
        if ((tid&31) == 0) { red[(tid>>5)*2] = xc; red[(tid>>5)*2+1] = xs; }
    }
    __syncthreads();
    if (tid < 64) {
        float Fr = red[0] + red[2];
        float Fi = -(red[1] + red[3]);
        float hp = x - (Fr*ct - Fi*st)*(1.f/64.f);
        g_hpp[base + tid] = hp * x;
    }
}

// ---------------- 2) conv1 (512->8) + sigmoid, partial-sum form ------------
__global__ void conv1_kernel(const float* __restrict__ w) {
    __shared__ float sw[4096];
    __shared__ float part[8][8][65];
    int b = blockIdx.x, v = blockIdx.y;
    int tid = threadIdx.x;
    for (int i = tid; i < 4096; i += 512) sw[i] = w[i];
    const float* X = (v < 2 ? g_p : g_hpp) + ((size_t)(((v&1)*BSZ + b)*DMODEL))*64;
    __syncthreads();
    int p = tid >> 6, s = tid & 63;
    float acc[8] = {};
    const float* Xp = X + (size_t)(p*64)*64 + s;
    #pragma unroll 8
    for (int j = 0; j < 64; j++) {
        float xv = Xp[(size_t)j*64];
        #pragma unroll
        for (int o = 0; o < 8; o++) acc[o] += sw[o*512 + p*64 + j] * xv;
    }
    #pragma unroll
    for (int o = 0; o < 8; o++) part[p][o][s] = acc[o];
    __syncthreads();
    int o = tid >> 6;
    float sum = 0.f;
    #pragma unroll
    for (int pp = 0; pp < 8; pp++) sum += part[pp][o][s];
    g_M[((size_t)(v*BSZ + b)*8 + o)*64 + s] = 1.f/(1.f + __expf(-sum));
}

// ---------------- 3) pattern loss: two-phase -------------------------------
__global__ void loss_partA() {
    __shared__ float sc[4][64];
    __shared__ float ssq[8];
    int blk = blockIdx.x, tid = threadIdx.x;
    int col = tid & 63, rg = tid >> 6;
    float s = 0.f, sq = 0.f;
    #pragma unroll
    for (int j = rg; j < 16; j += 4) {
        int vr = blk*16 + j;
        int row = (vr < 544) ? vr : vr + 224;
        float m = g_M[(size_t)row*64 + col];
        s += m; sq += m*m;
    }
    sc[rg][col] = s;
    #pragma unroll
    for (int off = 16; off; off >>= 1) sq += __shfl_down_sync(0xffffffffu, sq, off);
    if ((tid&31) == 0) ssq[tid>>5] = sq;
    __syncthreads();
    if (tid < 64)
        g_lpartc[blk*64 + tid] = sc[0][tid] + sc[1][tid] + sc[2][tid] + sc[3][tid];
    if (tid == 0) {
        float q = 0.f;
        #pragma unroll
        for (int wi = 0; wi < 8; wi++) q += ssq[wi];
        g_lpartq[blk] = q;
    }
}
__global__ void loss_partB(float* __restrict__ out_loss) {
    __shared__ float sred[2];
    int tid = threadIdx.x;
    float cs = 0.f;
    for (int b = 0; b < 36; b++) cs += g_lpartc[b*64 + tid];
    float v = cs*cs;
    #pragma unroll
    for (int off = 16; off; off >>= 1) v += __shfl_down_sync(0xffffffffu, v, off);
    if ((tid&31) == 0) sred[tid>>5] = v;
    __syncthreads();
    if (tid == 0) {
        float ss = sred[0] + sred[1];
        float sq = 0.f;
        for (int b = 0; b < 36; b++) sq += g_lpartq[b];
        out_loss[0] = (ss - sq)*0.5f/(576.f*575.f);
    }
}

// ---------------- 4) tokens -------------------------------------------------
__global__ void buildx_kernel(const float* __restrict__ pos, const float* __restrict__ c2w) {
    __shared__ float sw[4096];
    __shared__ float sm[16][8];
    int bt = blockIdx.x, b = blockIdx.y;
    int d = threadIdx.x;
    for (int i = d; i < 4096; i += 512) sw[i] = c2w[i];
    int which = (bt*16) >> 6;
    if (d < 128) {
        int i = d >> 3, o = d & 7;
        int t = bt*16 + i, s = t & 63;
        sm[i][o] = g_M[((size_t)(which*BSZ + b)*8 + o)*64 + s];
    }
    __syncthreads();
    float w0 = sw[d*8], w1 = sw[d*8+1], w2 = sw[d*8+2], w3 = sw[d*8+3];
    float w4 = sw[d*8+4], w5 = sw[d*8+5], w6 = sw[d*8+6], w7 = sw[d*8+7];
    #pragma unroll
    for (int i = 0; i < 16; i++) {
        int t = bt*16 + i, s = t & 63;
        float acc = w0*sm[i][0] + w1*sm[i][1] + w2*sm[i][2] + w3*sm[i][3]
                  + w4*sm[i][4] + w5*sm[i][5] + w6*sm[i][6] + w7*sm[i][7];
        float p = g_p[((size_t)((which*BSZ + b)*DMODEL + d))*64 + s];
        g_x[(size_t)(b*SEQL + t)*DMODEL + d] = pos[t*DMODEL + d] + acc*p;
    }
}

// ---------------- LayerNorm: warp-per-row ----------------------------------
template<bool PACK>
__global__ void ln_kernel(const float* __restrict__ x, void* __restrict__ y,
                          const float* __restrict__ w, const float* __restrict__ bsh) {
    int row = blockIdx.x*8 + (threadIdx.x >> 5);
    int lane = threadIdx.x & 31;
    const float4* xr = (const float4*)(x + (size_t)row*512);
    float4 v[4];
    float sum = 0.f, sq = 0.f;
    #pragma unroll
    for (int i = 0; i < 4; i++) {
        v[i] = xr[lane + 32*i];
        sum += v[i].x + v[i].y + v[i].z + v[i].w;
        sq  += v[i].x*v[i].x + v[i].y*v[i].y + v[i].z*v[i].z + v[i].w*v[i].w;
    }
    #pragma unroll
    for (int off = 16; off; off >>= 1) {
        sum += __shfl_xor_sync(0xffffffffu, sum, off);
        sq  += __shfl_xor_sync(0xffffffffu, sq,  off);
    }
    float mean = sum*(1.f/512.f);
    float inv = rsqrtf(sq*(1.f/512.f) - mean*mean + 1e-5f);
    #pragma unroll
    for (int i = 0; i < 4; i++) {
        int idx = lane + 32*i;
        float4 wv = ((const float4*)w)[idx];
        float4 bv = ((const float4*)bsh)[idx];
        float4 o;
        o.x = (v[i].x-mean)*inv*wv.x + bv.x;
        o.y = (v[i].y-mean)*inv*wv.y + bv.y;
        o.z = (v[i].z-mean)*inv*wv.z + bv.z;
        o.w = (v[i].w-mean)*inv*wv.w + bv.w;
        if (PACK) {
            ((uint2*)((uint32_t*)y + (size_t)row*256))[idx] =
                make_uint2(pkh2(o.x, o.y), pkh2(o.z, o.w));
        } else {
            ((float4*)((float*)y + (size_t)row*512))[idx] = o;
        }
    }
}

// ================= fp16 GEMM core: cp.async 4-stage, BK=32 ================
#define GEMM_AW 1280
#define GEMM_BW 2176
#define GEMM_STW (GEMM_AW + GEMM_BW)
#define GEMM_STB (GEMM_STW*4)
#define GEMM_SMEM (4*GEMM_STB)

template<int ACT, bool OUTHALF>
__device__ __forceinline__ void gemm_core(
    const uint32_t* __restrict__ A, const uint32_t* __restrict__ B,
    const float* __restrict__ bias, const float* __restrict__ resid,
    void* __restrict__ Cv, int N, int K, int bm, int bn, char* smem)
{
    uint32_t sb = smem_u32_of(smem);
    int tid = threadIdx.x;
    int warp = tid>>5, lane = tid&31;
    int wm = (warp&1)*32, wn = (warp>>1)*64;
    int lr = lane>>2, lc = lane&3;
    int K2 = K >> 1;

    float acc[2][8][4] = {};

    auto issue = [&](int stg, int kt) {
        uint32_t ab = sb + (uint32_t)stg*GEMM_STB;
        uint32_t bb = ab + GEMM_AW*4;
        int k0 = kt << 4;
        #pragma unroll
        for (int i = 0; i < 2; i++) {
            int c = tid + i*128;
            int row = c>>2, pos = (c&3)*4;
            const uint32_t* sa = A + (size_t)(bm+row)*K2 + k0 + pos;
            uint32_t da = ab + (uint32_t)(row*20 + pos)*4;
            asm volatile("cp.async.cg.shared.global [%0], [%1], 16;"
                         :: "r"(da), "l"(sa) : "memory");
        }
        #pragma unroll
        for (int i = 0; i < 4; i++) {
            int c = tid + i*128;
            int row = c>>5, pos = (c&31)*4;
            const uint32_t* sv = B + (size_t)(k0 + row)*N + bn + pos;
            uint32_t db = bb + (uint32_t)(row*136 + pos)*4;
            asm volatile("cp.async.cg.shared.global [%0], [%1], 16;"
                         :: "r"(db), "l"(sv) : "memory");
        }
        asm volatile("cp.async.commit_group;" ::: "memory");
    };

    int KT = K >> 5;
    issue(0, 0); issue(1, 1); issue(2, 2);

    for (int kt = 0; kt < KT; kt++) {
        asm volatile("cp.async.wait_group 2;" ::: "memory");
        __syncthreads();
        int nk = kt + 3;
        if (nk < KT) issue(nk & 3, nk);
        else asm volatile("cp.async.commit_group;" ::: "memory");

        const uint32_t* As = (const uint32_t*)(smem + (size_t)(kt&3)*GEMM_STB);
        const uint32_t* Bs = As + GEMM_AW;
        #pragma unroll
        for (int st = 0; st < 2; st++) {
            int cw = st*8 + lc;
            uint32_t a[2][4], b[8][2];
            #pragma unroll
            for (int mt = 0; mt < 2; mt++) {
                int r0 = wm + mt*16 + lr;
                a[mt][0] = As[r0*20 + cw];
                a[mt][1] = As[(r0+8)*20 + cw];
                a[mt][2] = As[r0*20 + cw + 4];
                a[mt][3] = As[(r0+8)*20 + cw + 4];
            }
            #pragma unroll
            for (int nt = 0; nt < 8; nt++) {
                int cn = wn + nt*8 + lr;
                b[nt][0] = Bs[cw*136 + cn];
                b[nt][1] = Bs[(cw+4)*136 + cn];
            }
            #pragma unroll
            for (int mt = 0; mt < 2; mt++)
                #pragma unroll
                for (int nt = 0; nt < 8; nt++)
                    mma_f16(acc[mt][nt], a[mt][0], a[mt][1], a[mt][2], a[mt][3],
                            b[nt][0], b[nt][1]);
        }
    }

    #pragma unroll
    for (int mt = 0; mt < 2; mt++) {
        int row0 = bm + wm + mt*16 + lr;
        #pragma unroll
        for (int nt = 0; nt < 8; nt++) {
            int col = bn + wn + nt*8 + 2*lc;
            float2 bb = *(const float2*)(bias + col);
            float v0 = acc[mt][nt][0] + bb.x, v1 = acc[mt][nt][1] + bb.y;
            float v2 = acc[mt][nt][2] + bb.x, v3 = acc[mt][nt][3] + bb.y;
            if (ACT == 1) {
                v0 *= normcdff(v0); v1 *= normcdff(v1);
                v2 *= normcdff(v2); v3 *= normcdff(v3);
            }
            if (OUTHALF) {
                uint32_t* C16 = (uint32_t*)Cv;
                int Nw = N >> 1;
                C16[(size_t)row0*Nw + (col>>1)]     = pkh2(v0, v1);
                C16[(size_t)(row0+8)*Nw + (col>>1)] = pkh2(v2, v3);
            } else {
                float* C = (float*)Cv;
                size_t o0 = (size_t)row0*N + col;
                size_t o1 = (size_t)(row0+8)*N + col;
                if (ACT == 2) {
                    float2 r0 = *(const float2*)(resid + o0);
                    float2 r1 = *(const float2*)(resid + o1);
                    v0 += r0.x; v1 += r0.y; v2 += r1.x; v3 += r1.y;
                }
                *(float2*)(C + o0) = make_float2(v0, v1);
                *(float2*)(C + o1) = make_float2(v2, v3);
            }
        }
    }
}

template<int ACT, bool OUTHALF>
__global__ void __launch_bounds__(128, 3) gemm_kernel(
    const uint32_t* __restrict__ A, const uint32_t* __restrict__ B,
    const float* __restrict__ bias, const float* __restrict__ resid,
    void* __restrict__ C, int N, int K)
{
    extern __shared__ char smem[];
    gemm_core<ACT, OUTHALF>(A, B, bias, resid, C, N, K,
                            blockIdx.y*64, blockIdx.x*128, smem);
}

// fused QKV: grid (12, 64)
__global__ void __launch_bounds__(128, 3) gemm_qkv_kernel(
    const uint32_t* __restrict__ A,
    const uint32_t* __restrict__ wq, const uint32_t* __restrict__ wk,
    const uint32_t* __restrict__ wv,
    const float* __restrict__ bq, const float* __restrict__ bk,
    const float* __restrict__ bv,
    uint32_t* __restrict__ q, uint32_t* __restrict__ k, uint32_t* __restrict__ v)
{
    extern __shared__ char smem[];
    int sel = blockIdx.x >> 2;
    int bn = (blockIdx.x & 3)*128;
    const uint32_t* B = (sel == 0) ? wq : (sel == 1) ? wk : wv;
    const float* bias = (sel == 0) ? bq : (sel == 1) ? bk : bv;
    uint32_t* C = (sel == 0) ? q : (sel == 1) ? k : v;
    gemm_core<0, true>(A, B, bias, nullptr, C, 512, 512, blockIdx.y*64, bn, smem);
}

// ---------------- fused fp16 attention per (b,h) (R14 proven) --------------
#define ATTN_SMEM ((64*72 + 128*36 + 128*36)*4)   // 55296 B
__global__ void __launch_bounds__(256) attn_kernel() {
    extern __shared__ uint32_t smw[];
    uint32_t* Vs = smw;
    uint32_t* Qs = smw + 64*72;
    uint32_t* Ks = Qs + 128*36;
    uint32_t* Ps = Qs;   // [128][68]

    int bh = blockIdx.x, b = bh >> 3, h = bh & 7;
    int tid = threadIdx.x, warp = tid>>5, lane = tid&31;
    int lr = lane>>2, lc = lane&3;
    const uint32_t* qp = g_qh + (size_t)(b*SEQL)*256 + h*32;
    const uint32_t* kp = g_kh + (size_t)(b*SEQL)*256 + h*32;
    const uint32_t* vp = g_vh + (size_t)(b*SEQL)*256 + h*32;

    #pragma unroll
    for (int i = 0; i < 4; i++) {
        int idx = tid + i*256;
        int s = idx >> 3, pos = (idx & 7)*4;
        *(uint4*)&Qs[s*36 + pos] = *(const uint4*)(qp + (size_t)s*256 + pos);
        *(uint4*)&Ks[s*36 + pos] = *(const uint4*)(kp + (size_t)s*256 + pos);
    }
    #pragma unroll
    for (int i = 0; i < 8; i++) {
        int t = tid + i*256;
        int sp = t >> 5, dp = t & 31;
        uint32_t w0 = vp[(size_t)(2*sp)*256 + dp];
        uint32_t w1 = vp[(size_t)(2*sp+1)*256 + dp];
        Vs[sp*72 + 2*dp]     = __byte_perm(w0, w1, 0x5410);
        Vs[sp*72 + 2*dp + 1] = __byte_perm(w0, w1, 0x7632);
    }
    __syncthreads();

    int qr = warp*16 + lr;
    float accs[16][4] = {};
    #pragma unroll
    for (int st = 0; st < 4; st++) {
        int cw = st*8 + lc;
        uint32_t a0 = Qs[qr*36 + cw],     a1 = Qs[(qr+8)*36 + cw];
        uint32_t a2 = Qs[qr*36 + cw + 4], a3 = Qs[(qr+8)*36 + cw + 4];
        #pragma unroll
        for (int nt = 0; nt < 16; nt++) {
            int kn = nt*8 + lr;
            uint32_t b0 = Ks[kn*36 + cw];
            uint32_t b1 = Ks[kn*36 + cw + 4];
            mma_f16(accs[nt], a0, a1, a2, a3, b0, b1);
        }
    }
    float m0 = -1e30f, m1 = -1e30f;
    #pragma unroll
    for (int nt = 0; nt < 16; nt++) {
        #pragma unroll
        for (int j = 0; j < 4; j++) accs[nt][j] *= 0.125f;
        m0 = fmaxf(m0, fmaxf(accs[nt][0], accs[nt][1]));
        m1 = fmaxf(m1, fmaxf(accs[nt][2], accs[nt][3]));
    }
    m0 = fmaxf(m0, __shfl_xor_sync(0xffffffffu, m0, 1));
    m0 = fmaxf(m0, __shfl_xor_sync(0xffffffffu, m0, 2));
    m1 = fmaxf(m1, __shfl_xor_sync(0xffffffffu, m1, 1));
    m1 = fmaxf(m1, __shfl_xor_sync(0xffffffffu, m1, 2));
    float s0 = 0.f, s1 = 0.f;
    #pragma unroll
    for (int nt = 0; nt < 16; nt++) {
        accs[nt][0] = __expf(accs[nt][0] - m0);
        accs[nt][1] = __expf(accs[nt][1] - m0);
        accs[nt][2] = __expf(accs[nt][2] - m1);
        accs[nt][3] = __expf(accs[nt][3] - m1);
        s0 += accs[nt][0] + accs[nt][1];
        s1 += accs[nt][2] + accs[nt][3];
    }
    s0 += __shfl_xor_sync(0xffffffffu, s0, 1);
    s0 += __shfl_xor_sync(0xffffffffu, s0, 2);
    s1 += __shfl_xor_sync(0xffffffffu, s1, 1);
    s1 += __shfl_xor_sync(0xffffffffu, s1, 2);
    float i0 = 1.f/s0, i1 = 1.f/s1;

    __syncthreads();
    #pragma unroll
    for (int nt = 0; nt < 16; nt++) {
        int wdi = nt*4 + lc;
        Ps[qr*68 + wdi]     = pkh2(accs[nt][0]*i0, accs[nt][1]*i0);
        Ps[(qr+8)*68 + wdi] = pkh2(accs[nt][2]*i1, accs[nt][3]*i1);
    }
    __syncthreads();

    float acco[8][4] = {};
    #pragma unroll
    for (int kk = 0; kk < 8; kk++) {
        int cw = kk*8 + lc;
        uint32_t a0 = Ps[qr*68 + cw],     a1 = Ps[(qr+8)*68 + cw];
        uint32_t a2 = Ps[qr*68 + cw + 4], a3 = Ps[(qr+8)*68 + cw + 4];
        #pragma unroll
        for (int nt = 0; nt < 8; nt++) {
            int dn = nt*8 + lr;
            uint32_t b0 = Vs[cw*72 + dn];
            uint32_t b1 = Vs[(cw+4)*72 + dn];
            mma_f16(acco[nt], a0, a1, a2, a3, b0, b1);
        }
    }
    uint32_t* op = g_oh + (size_t)(b*SEQL)*256 + h*32;
    #pragma unroll
    for (int nt = 0; nt < 8; nt++) {
        int wdi = nt*4 + lc;
        op[(size_t)qr*256 + wdi]     = pkh2(acco[nt][0], acco[nt][1]);
        op[(size_t)(qr+8)*256 + wdi] = pkh2(acco[nt][2], acco[nt][3]);
    }
}

// ---------------- bilinear upsample 8x8 -> 32x32, 8-d blocks ---------------
// grid (64, 32, 2), 256 thr. Block handles d in [d0,d0+8), one (b, which).
// Loads g_ln[ (b*128 + which*64 + s)*512 + d0..d0+7 ] as contiguous 8-float runs.
__global__ void upsample_kernel(float* __restrict__ out) {
    __shared__ float g[8][65];   // [dloc][s]
    int d0 = blockIdx.x*8, b = blockIdx.y, which = blockIdx.z;
    int tid = threadIdx.x;
    {
        int s = tid >> 3, dl = tid & 7;        // 256 thr covers 32 s x 8 d
        #pragma unroll
        for (int i = 0; i < 2; i++) {
            int ss = s + i*32;
            g[dl][ss] = g_ln[(size_t)(b*SEQL + which*64 + ss)*512 + d0 + dl];
        }
    }
    __syncthreads();
    int dl = tid >> 5, lane = tid & 31;        // warp per d
    float* op = out + (size_t)which*(BSZ*512*1024)
                    + ((size_t)(b*512 + d0 + dl))*1024;
    const float* gr = g[dl];
    #pragma unroll
    for (int r = 0; r < 32; r++) {
        int pix = lane + r*32;
        int oy = pix >> 5, ox = pix & 31;
        float cy = (oy + 0.5f)*0.25f - 0.5f;
        float cx = (ox + 0.5f)*0.25f - 0.5f;
        int y0 = (int)floorf(cy); float wy = cy - y0;
        int x0 = (int)floorf(cx); float wx = cx - x0;
        int y1 = min(y0+1, 7); y0 = max(y0, 0);
        int x1 = min(x0+1, 7); x0 = max(x0, 0);
        float v00 = gr[y0*8+x0], v01 = gr[y0*8+x1], v10 = gr[y1*8+x0], v11 = gr[y1*8+x1];
        op[pix] = (1.f-wy)*((1.f-wx)*v00 + wx*v01) + wy*((1.f-wx)*v10 + wx*v11);
    }
}

// ---------------- launcher --------------------------------------------------
extern "C" void kernel_launch(void* const* d_in, const int* in_sizes, int n_in,
                              void* d_out, int out_size) {
    const float* rgb  = (const float*)d_in[0];
    const float* ir   = (const float*)d_in[1];
    const float* pos  = (const float*)d_in[2];
    const float* c1w  = (const float*)d_in[3];
    const float* c2w  = (const float*)d_in[4];
    const float* ln1w = (const float*)d_in[5];
    const float* ln1b = (const float*)d_in[6];
    const float* Wq   = (const float*)d_in[7];
    const float* bq   = (const float*)d_in[8];
    const float* Wk   = (const float*)d_in[9];
    const float* bk   = (const float*)d_in[10];
    const float* Wv   = (const float*)d_in[11];
    const float* bv   = (const float*)d_in[12];
    const float* Wo   = (const float*)d_in[13];
    const float* bo   = (const float*)d_in[14];
    const float* ln2w = (const float*)d_in[15];
    const float* ln2b = (const float*)d_in[16];
    const float* W1   = (const float*)d_in[17];
    const float* b1   = (const float*)d_in[18];
    const float* W2   = (const float*)d_in[19];
    const float* b2   = (const float*)d_in[20];
    const float* lnfw = (const float*)d_in[21];
    const float* lnfb = (const float*)d_in[22];
    float* out = (float*)d_out;

    float *p_x, *p_ln;
    uint32_t *p_lnh, *p_qh, *p_kh, *p_vh, *p_oh, *p_hh;
    uint32_t *p_wq, *p_wk, *p_wv, *p_wo, *p_w1, *p_w2;
    cudaGetSymbolAddress((void**)&p_x,   g_x);
    cudaGetSymbolAddress((void**)&p_ln,  g_ln);
    cudaGetSymbolAddress((void**)&p_lnh, g_lnh);
    cudaGetSymbolAddress((void**)&p_qh,  g_qh);
    cudaGetSymbolAddress((void**)&p_kh,  g_kh);
    cudaGetSymbolAddress((void**)&p_vh,  g_vh);
    cudaGetSymbolAddress((void**)&p_oh,  g_oh);
    cudaGetSymbolAddress((void**)&p_hh,  g_hh);
    cudaGetSymbolAddress((void**)&p_wq,  g_wq);
    cudaGetSymbolAddress((void**)&p_wk,  g_wk);
    cudaGetSymbolAddress((void**)&p_wv,  g_wv);
    cudaGetSymbolAddress((void**)&p_wo,  g_wo);
    cudaGetSymbolAddress((void**)&p_w1,  g_w1);
    cudaGetSymbolAddress((void**)&p_w2,  g_w2);

    cudaFuncSetAttribute(attn_kernel, cudaFuncAttributeMaxDynamicSharedMemorySize, ATTN_SMEM);
    cudaFuncSetAttribute(gemm_qkv_kernel, cudaFuncAttributeMaxDynamicSharedMemorySize, GEMM_SMEM);
    cudaFuncSetAttribute(gemm_kernel<2,false>, cudaFuncAttributeMaxDynamicSharedMemorySize, GEMM_SMEM);
    cudaFuncSetAttribute(gemm_kernel<1,true>, cudaFuncAttributeMaxDynamicSharedMemorySize, GEMM_SMEM);

    pack_all<<<(PACK_TOTAL+255)/256, 256>>>(Wq, Wk, Wv, Wo, W1, W2,
                                            p_wq, p_wk, p_wv, p_wo, p_w1, p_w2);

    pool_hp_kernel<<<dim3(DMODEL, BSZ, 2), 256>>>(rgb, ir);
    conv1_kernel<<<dim3(BSZ, 4), 512>>>(c1w);
    loss_partA<<<36, 256>>>();
    loss_partB<<<1, 64>>>(out + (size_t)2*BSZ*512*1024);
    buildx_kernel<<<dim3(8, BSZ), 512>>>(pos, c2w);

    dim3 gqkv(12, NTOK/64);          // 768 CTAs
    dim3 g512(4, NTOK/64);           // 256 CTAs
    dim3 g2048(16, NTOK/64);         // 1024 CTAs

    for (int l = 0; l < NLAYER; l++) {
        size_t wOff = (size_t)l*(DMODEL/2)*DMODEL;
        size_t w1Off = (size_t)l*(DMODEL/2)*HID;
        size_t w2Off = (size_t)l*(HID/2)*DMODEL;
        size_t bOff = (size_t)l*512, b1Off = (size_t)l*2048;
        ln_kernel<true><<<NTOK/8, 256>>>(p_x, p_lnh, ln1w + bOff, ln1b + bOff);
        gemm_qkv_kernel<<<gqkv, 128, GEMM_SMEM>>>(p_lnh,
            p_wq + wOff, p_wk + wOff, p_wv + wOff,
            bq + bOff, bk + bOff, bv + bOff, p_qh, p_kh, p_vh);
        attn_kernel<<<BSZ*NHEAD, 256, ATTN_SMEM>>>();
        gemm_kernel<2,false><<<g512, 128, GEMM_SMEM>>>(p_oh, p_wo + wOff,
            bo + bOff, p_x, p_x, 512, 512);
        ln_kernel<true><<<NTOK/8, 256>>>(p_x, p_lnh, ln2w + bOff, ln2b + bOff);
        gemm_kernel<1,true><<<g2048, 128, GEMM_SMEM>>>(p_lnh, p_w1 + w1Off,
            b1 + b1Off, nullptr, p_hh, 2048, 512);
        gemm_kernel<2,false><<<g512, 128, GEMM_SMEM>>>(p_hh, p_w2 + w2Off,
            b2 + bOff, p_x, p_x, 512, 2048);
    }
    ln_kernel<false><<<NTOK/8, 256>>>(p_x, p_ln, lnfw, lnfb);
    upsample_kernel<<<dim3(64, BSZ, 2), 256>>>(out);
}

// round 17
// speedup vs baseline: 1.0344x; 1.0117x over previous
#include <cuda_runtime.h>
#include <cuda_fp16.h>
#include <math.h>
#include <stdint.h>

// ---------------- problem constants ----------------
#define BSZ   32
#define DMODEL 512
#define SEQL  128
#define NTOK  (BSZ*SEQL)     // 4096
#define NHEAD 8
#define HID   2048
#define NLAYER 8

// ---------------- scratch ----------------
__device__ float g_p  [2*BSZ*DMODEL*64];
__device__ float g_hpp[2*BSZ*DMODEL*64];
__device__ float g_M  [4*BSZ*8*64];
__device__ float g_x  [NTOK*DMODEL];
__device__ float g_ln [NTOK*DMODEL];
__device__ float g_lpartc[36*64];
__device__ float g_lpartq[36];
__device__ uint32_t g_lnh[NTOK*DMODEL/2];
__device__ uint32_t g_qh [NTOK*DMODEL/2];
__device__ uint32_t g_kh [NTOK*DMODEL/2];
__device__ uint32_t g_vh [NTOK*DMODEL/2];
__device__ uint32_t g_oh [NTOK*DMODEL/2];
__device__ uint32_t g_hh [NTOK*HID/2];
__device__ uint32_t g_wq[NLAYER*DMODEL/2*DMODEL];
__device__ uint32_t g_wk[NLAYER*DMODEL/2*DMODEL];
__device__ uint32_t g_wv[NLAYER*DMODEL/2*DMODEL];
__device__ uint32_t g_wo[NLAYER*DMODEL/2*DMODEL];
__device__ uint32_t g_w1[NLAYER*DMODEL/2*HID];
__device__ uint32_t g_w2[NLAYER*HID/2*DMODEL];

__constant__ float COS8[8] = {1.f,-0.70710678118654752f,0.f,0.70710678118654752f,
                              -1.f,0.70710678118654752f,0.f,-0.70710678118654752f};
__constant__ float SIN8[8] = {0.f,0.70710678118654752f,-1.f,0.70710678118654752f,
                              0.f,-0.70710678118654752f,1.f,-0.70710678118654752f};

// ---------------- helpers ----------------
__device__ __forceinline__ uint32_t pkh2(float a, float b) {
    __half2 h = __floats2half2_rn(a, b);
    return *reinterpret_cast<uint32_t*>(&h);
}
__device__ __forceinline__ void mma_f16(float* c, uint32_t a0, uint32_t a1,
                                        uint32_t a2, uint32_t a3,
                                        uint32_t b0, uint32_t b1) {
    asm volatile(
        "mma.sync.aligned.m16n8k16.row.col.f32.f16.f16.f32 "
        "{%0,%1,%2,%3},{%4,%5,%6,%7},{%8,%9},{%0,%1,%2,%3};"
        : "+f"(c[0]), "+f"(c[1]), "+f"(c[2]), "+f"(c[3])
        : "r"(a0), "r"(a1), "r"(a2), "r"(a3), "r"(b0), "r"(b1));
}
__device__ __forceinline__ uint32_t smem_u32_of(const void* p) {
    uint32_t a;
    asm("{ .reg .u64 t; cvta.to.shared.u64 t, %1; cvt.u32.u64 %0, t; }" : "=r"(a) : "l"(p));
    return a;
}

// ---------------- fused weight packing ----------
#define QKV_U4 (NLAYER*256*128)
#define W1_U4  (NLAYER*256*512)
#define PACK_TOTAL (4*QKV_U4 + 2*W1_U4)
__global__ void pack_all(
    const float* __restrict__ Wq, const float* __restrict__ Wk,
    const float* __restrict__ Wv, const float* __restrict__ Wo,
    const float* __restrict__ W1, const float* __restrict__ W2,
    uint32_t* __restrict__ oq, uint32_t* __restrict__ ok,
    uint32_t* __restrict__ ov, uint32_t* __restrict__ oo,
    uint32_t* __restrict__ o1, uint32_t* __restrict__ o2)
{
    int i = blockIdx.x*256 + threadIdx.x;
    if (i >= PACK_TOTAL) return;
    const float* W; uint32_t* out; int local, N;
    if (i < 4*QKV_U4) {
        int sel = i >> 18;
        local = i & (QKV_U4 - 1);
        N = 512;
        W = (sel == 0) ? Wq : (sel == 1) ? Wk : (sel == 2) ? Wv : Wo;
        out = (sel == 0) ? oq : (sel == 1) ? ok : (sel == 2) ? ov : oo;
    } else if (i < 4*QKV_U4 + W1_U4) {
        local = i - 4*QKV_U4; N = 2048; W = W1; out = o1;
    } else {
        local = i - 4*QKV_U4 - W1_U4; N = 512; W = W2; out = o2;
    }
    int nw4 = N >> 2;
    int k2 = local / nw4;
    int n  = (local - k2*nw4)*4;
    float4 r0 = *(const float4*)(W + (size_t)(2*k2)*N + n);
    float4 r1 = *(const float4*)(W + (size_t)(2*k2+1)*N + n);
    ((uint4*)out)[local] = make_uint4(pkh2(r0.x, r1.x), pkh2(r0.y, r1.y),
                                      pkh2(r0.z, r1.z), pkh2(r0.w, r1.w));
}

// ---------------- 1) avgpool 4x4 + single-bin highpass ----------
__global__ void pool_hp_kernel(const float* __restrict__ rgb, const float* __restrict__ ir) {
    __shared__ float sp[64];
    __shared__ float red[4];
    int c = blockIdx.x, b = blockIdx.y, src = blockIdx.z;
    int tid = threadIdx.x;
    const float* in = (src == 0 ? rgb : ir) + ((size_t)(b*DMODEL + c))*1024;
    float4 v = ((const float4*)in)[tid];
    float t = v.x + v.y + v.z + v.w;
    t += __shfl_xor_sync(0xffffffffu, t, 8);
    t += __shfl_xor_sync(0xffffffffu, t, 16);
    int lane = tid & 31, w = tid >> 5;
    if (lane < 8) sp[w*8 + lane] = t*(1.f/16.f);
    __syncthreads();
    size_t base = ((size_t)((src*BSZ + b)*DMODEL + c))*64;
    float x = 0.f, ct = 0.f, st = 0.f;
    if (tid < 64) {
        x = sp[tid];
        g_p[base + tid] = x;
        int idx = (3*((tid>>3) + (tid&7))) & 7;
        ct = COS8[idx]; st = SIN8[idx];
    }
    float xc = x*ct, xs = x*st;
    if (tid < 64) {
        #pragma unroll
        for (int off = 16; off; off >>= 1) {
            xc += __shfl_down_sync(0xffffffffu, xc, off);
            xs += __shfl_down_sync(0xffffffffu, xs, off);
        }
        if ((tid&31) == 0) { red[(tid>>5)*2] = xc; red[(tid>>5)*2+1] = xs; }
    }
    __syncthreads();
    if (tid < 64) {
        float Fr = red[0] + red[2];
        float Fi = -(red[1] + red[3]);
        float hp = x - (Fr*ct - Fi*st)*(1.f/64.f);
        g_hpp[base + tid] = hp * x;
    }
}

// ---------------- 2) conv1 (512->8) + sigmoid, partial-sum form ------------
__global__ void conv1_kernel(const float* __restrict__ w) {
    __shared__ float sw[4096];
    __shared__ float part[8][8][65];
    int b = blockIdx.x, v = blockIdx.y;
    int tid = threadIdx.x;
    for (int i = tid; i < 4096; i += 512) sw[i] = w[i];
    const float* X = (v < 2 ? g_p : g_hpp) + ((size_t)(((v&1)*BSZ + b)*DMODEL))*64;
    __syncthreads();
    int p = tid >> 6, s = tid & 63;
    float acc[8] = {};
    const float* Xp = X + (size_t)(p*64)*64 + s;
    #pragma unroll 8
    for (int j = 0; j < 64; j++) {
        float xv = Xp[(size_t)j*64];
        #pragma unroll
        for (int o = 0; o < 8; o++) acc[o] += sw[o*512 + p*64 + j] * xv;
    }
    #pragma unroll
    for (int o = 0; o < 8; o++) part[p][o][s] = acc[o];
    __syncthreads();
    int o = tid >> 6;
    float sum = 0.f;
    #pragma unroll
    for (int pp = 0; pp < 8; pp++) sum += part[pp][o][s];
    g_M[((size_t)(v*BSZ + b)*8 + o)*64 + s] = 1.f/(1.f + __expf(-sum));
}

// ---------------- 3) pattern loss: two-phase -------------------------------
__global__ void loss_partA() {
    __shared__ float sc[4][64];
    __shared__ float ssq[8];
    int blk = blockIdx.x, tid = threadIdx.x;
    int col = tid & 63, rg = tid >> 6;
    float s = 0.f, sq = 0.f;
    #pragma unroll
    for (int j = rg; j < 16; j += 4) {
        int vr = blk*16 + j;
        int row = (vr < 544) ? vr : vr + 224;
        float m = g_M[(size_t)row*64 + col];
        s += m; sq += m*m;
    }
    sc[rg][col] = s;
    #pragma unroll
    for (int off = 16; off; off >>= 1) sq += __shfl_down_sync(0xffffffffu, sq, off);
    if ((tid&31) == 0) ssq[tid>>5] = sq;
    __syncthreads();
    if (tid < 64)
        g_lpartc[blk*64 + tid] = sc[0][tid] + sc[1][tid] + sc[2][tid] + sc[3][tid];
    if (tid == 0) {
        float q = 0.f;
        #pragma unroll
        for (int wi = 0; wi < 8; wi++) q += ssq[wi];
        g_lpartq[blk] = q;
    }
}
__global__ void loss_partB(float* __restrict__ out_loss) {
    __shared__ float sred[2];
    int tid = threadIdx.x;
    float cs = 0.f;
    for (int b = 0; b < 36; b++) cs += g_lpartc[b*64 + tid];
    float v = cs*cs;
    #pragma unroll
    for (int off = 16; off; off >>= 1) v += __shfl_down_sync(0xffffffffu, v, off);
    if ((tid&31) == 0) sred[tid>>5] = v;
    __syncthreads();
    if (tid == 0) {
        float ss = sred[0] + sred[1];
        float sq = 0.f;
        for (int b = 0; b < 36; b++) sq += g_lpartq[b];
        out_loss[0] = (ss - sq)*0.5f/(576.f*575.f);
    }
}

// ---------------- 4) tokens: coalesced g_p staging --------------------------
// grid (4, 32, 2), 512 thr. Block handles 16 tokens (s in [sg*16, sg*16+16))
// of (b, which). g_p slice staged [512 d][16 s] via full-sector loads.
__global__ void buildx_kernel(const float* __restrict__ pos, const float* __restrict__ c2w) {
    __shared__ float gp[512][17];
    __shared__ float sm[16][8];
    int sg = blockIdx.x, b = blockIdx.y, which = blockIdx.z;
    int d = threadIdx.x;
    size_t pbase = ((size_t)((which*BSZ + b)*DMODEL))*64 + sg*16;
    #pragma unroll
    for (int i = 0; i < 16; i++) {
        int e = d + i*512;
        int de = e >> 4, sl = e & 15;
        gp[de][sl] = g_p[pbase + (size_t)de*64 + sl];
    }
    if (d < 128) {
        int i = d >> 3, o = d & 7;
        int s = sg*16 + i;
        sm[i][o] = g_M[((size_t)(which*BSZ + b)*8 + o)*64 + s];
    }
    __syncthreads();
    float4 wa = *(const float4*)(c2w + d*8);
    float4 wb = *(const float4*)(c2w + d*8 + 4);
    #pragma unroll
    for (int i = 0; i < 16; i++) {
        int t = which*64 + sg*16 + i;
        float acc = wa.x*sm[i][0] + wa.y*sm[i][1] + wa.z*sm[i][2] + wa.w*sm[i][3]
                  + wb.x*sm[i][4] + wb.y*sm[i][5] + wb.z*sm[i][6] + wb.w*sm[i][7];
        g_x[(size_t)(b*SEQL + t)*DMODEL + d] = pos[t*DMODEL + d] + acc*gp[d][i];
    }
}

// ---------------- LayerNorm: warp-per-row ----------------------------------
template<bool PACK>
__global__ void ln_kernel(const float* __restrict__ x, void* __restrict__ y,
                          const float* __restrict__ w, const float* __restrict__ bsh) {
    int row = blockIdx.x*8 + (threadIdx.x >> 5);
    int lane = threadIdx.x & 31;
    const float4* xr = (const float4*)(x + (size_t)row*512);
    float4 v[4];
    float sum = 0.f, sq = 0.f;
    #pragma unroll
    for (int i = 0; i < 4; i++) {
        v[i] = xr[lane + 32*i];
        sum += v[i].x + v[i].y + v[i].z + v[i].w;
        sq  += v[i].x*v[i].x + v[i].y*v[i].y + v[i].z*v[i].z + v[i].w*v[i].w;
    }
    #pragma unroll
    for (int off = 16; off; off >>= 1) {
        sum += __shfl_xor_sync(0xffffffffu, sum, off);
        sq  += __shfl_xor_sync(0xffffffffu, sq,  off);
    }
    float mean = sum*(1.f/512.f);
    float inv = rsqrtf(sq*(1.f/512.f) - mean*mean + 1e-5f);
    #pragma unroll
    for (int i = 0; i < 4; i++) {
        int idx = lane + 32*i;
        float4 wv = ((const float4*)w)[idx];
        float4 bv = ((const float4*)bsh)[idx];
        float4 o;
        o.x = (v[i].x-mean)*inv*wv.x + bv.x;
        o.y = (v[i].y-mean)*inv*wv.y + bv.y;
        o.z = (v[i].z-mean)*inv*wv.z + bv.z;
        o.w = (v[i].w-mean)*inv*wv.w + bv.w;
        if (PACK) {
            ((uint2*)((uint32_t*)y + (size_t)row*256))[idx] =
                make_uint2(pkh2(o.x, o.y), pkh2(o.z, o.w));
        } else {
            ((float4*)((float*)y + (size_t)row*512))[idx] = o;
        }
    }
}

// ================= fp16 GEMM core: cp.async 4-stage, BK=32 ================
#define GEMM_AW 1280
#define GEMM_BW 2176
#define GEMM_STW (GEMM_AW + GEMM_BW)
#define GEMM_STB (GEMM_STW*4)
#define GEMM_SMEM (4*GEMM_STB)

template<int ACT, bool OUTHALF>
__device__ __forceinline__ void gemm_core(
    const uint32_t* __restrict__ A, const uint32_t* __restrict__ B,
    const float* __restrict__ bias, const float* __restrict__ resid,
    void* __restrict__ Cv, int N, int K, int bm, int bn, char* smem)
{
    uint32_t sb = smem_u32_of(smem);
    int tid = threadIdx.x;
    int warp = tid>>5, lane = tid&31;
    int wm = (warp&1)*32, wn = (warp>>1)*64;
    int lr = lane>>2, lc = lane&3;
    int K2 = K >> 1;

    float acc[2][8][4] = {};

    auto issue = [&](int stg, int kt) {
        uint32_t ab = sb + (uint32_t)stg*GEMM_STB;
        uint32_t bb = ab + GEMM_AW*4;
        int k0 = kt << 4;
        #pragma unroll
        for (int i = 0; i < 2; i++) {
            int c = tid + i*128;
            int row = c>>2, pos = (c&3)*4;
            const uint32_t* sa = A + (size_t)(bm+row)*K2 + k0 + pos;
            uint32_t da = ab + (uint32_t)(row*20 + pos)*4;
            asm volatile("cp.async.cg.shared.global [%0], [%1], 16;"
                         :: "r"(da), "l"(sa) : "memory");
        }
        #pragma unroll
        for (int i = 0; i < 4; i++) {
            int c = tid + i*128;
            int row = c>>5, pos = (c&31)*4;
            const uint32_t* sv = B + (size_t)(k0 + row)*N + bn + pos;
            uint32_t db = bb + (uint32_t)(row*136 + pos)*4;
            asm volatile("cp.async.cg.shared.global [%0], [%1], 16;"
                         :: "r"(db), "l"(sv) : "memory");
        }
        asm volatile("cp.async.commit_group;" ::: "memory");
    };

    int KT = K >> 5;
    issue(0, 0); issue(1, 1); issue(2, 2);

    for (int kt = 0; kt < KT; kt++) {
        asm volatile("cp.async.wait_group 2;" ::: "memory");
        __syncthreads();
        int nk = kt + 3;
        if (nk < KT) issue(nk & 3, nk);
        else asm volatile("cp.async.commit_group;" ::: "memory");

        const uint32_t* As = (const uint32_t*)(smem + (size_t)(kt&3)*GEMM_STB);
        const uint32_t* Bs = As + GEMM_AW;
        #pragma unroll
        for (int st = 0; st < 2; st++) {
            int cw = st*8 + lc;
            uint32_t a[2][4], b[8][2];
            #pragma unroll
            for (int mt = 0; mt < 2; mt++) {
                int r0 = wm + mt*16 + lr;
                a[mt][0] = As[r0*20 + cw];
                a[mt][1] = As[(r0+8)*20 + cw];
                a[mt][2] = As[r0*20 + cw + 4];
                a[mt][3] = As[(r0+8)*20 + cw + 4];
            }
            #pragma unroll
            for (int nt = 0; nt < 8; nt++) {
                int cn = wn + nt*8 + lr;
                b[nt][0] = Bs[cw*136 + cn];
                b[nt][1] = Bs[(cw+4)*136 + cn];
            }
            #pragma unroll
            for (int mt = 0; mt < 2; mt++)
                #pragma unroll
                for (int nt = 0; nt < 8; nt++)
                    mma_f16(acc[mt][nt], a[mt][0], a[mt][1], a[mt][2], a[mt][3],
                            b[nt][0], b[nt][1]);
        }
    }

    #pragma unroll
    for (int mt = 0; mt < 2; mt++) {
        int row0 = bm + wm + mt*16 + lr;
        #pragma unroll
        for (int nt = 0; nt < 8; nt++) {
            int col = bn + wn + nt*8 + 2*lc;
            float2 bb = *(const float2*)(bias + col);
            float v0 = acc[mt][nt][0] + bb.x, v1 = acc[mt][nt][1] + bb.y;
            float v2 = acc[mt][nt][2] + bb.x, v3 = acc[mt][nt][3] + bb.y;
            if (ACT == 1) {
                v0 *= normcdff(v0); v1 *= normcdff(v1);
                v2 *= normcdff(v2); v3 *= normcdff(v3);
            }
            if (OUTHALF) {
                uint32_t* C16 = (uint32_t*)Cv;
                int Nw = N >> 1;
                C16[(size_t)row0*Nw + (col>>1)]     = pkh2(v0, v1);
                C16[(size_t)(row0+8)*Nw + (col>>1)] = pkh2(v2, v3);
            } else {
                float* C = (float*)Cv;
                size_t o0 = (size_t)row0*N + col;
                size_t o1 = (size_t)(row0+8)*N + col;
                if (ACT == 2) {
                    float2 r0 = *(const float2*)(resid + o0);
                    float2 r1 = *(const float2*)(resid + o1);
                    v0 += r0.x; v1 += r0.y; v2 += r1.x; v3 += r1.y;
                }
                *(float2*)(C + o0) = make_float2(v0, v1);
                *(float2*)(C + o1) = make_float2(v2, v3);
            }
        }
    }
}

template<int ACT, bool OUTHALF>
__global__ void __launch_bounds__(128, 3) gemm_kernel(
    const uint32_t* __restrict__ A, const uint32_t* __restrict__ B,
    const float* __restrict__ bias, const float* __restrict__ resid,
    void* __restrict__ C, int N, int K)
{
    extern __shared__ char smem[];
    gemm_core<ACT, OUTHALF>(A, B, bias, resid, C, N, K,
                            blockIdx.y*64, blockIdx.x*128, smem);
}

// fused QKV: grid (12, 64)
__global__ void __launch_bounds__(128, 3) gemm_qkv_kernel(
    const uint32_t* __restrict__ A,
    const uint32_t* __restrict__ wq, const uint32_t* __restrict__ wk,
    const uint32_t* __restrict__ wv,
    const float* __restrict__ bq, const float* __restrict__ bk,
    const float* __restrict__ bv,
    uint32_t* __restrict__ q, uint32_t* __restrict__ k, uint32_t* __restrict__ v)
{
    extern __shared__ char smem[];
    int sel = blockIdx.x >> 2;
    int bn = (blockIdx.x & 3)*128;
    const uint32_t* B = (sel == 0) ? wq : (sel == 1) ? wk : wv;
    const float* bias = (sel == 0) ? bq : (sel == 1) ? bk : bv;
    uint32_t* C = (sel == 0) ? q : (sel == 1) ? k : v;
    gemm_core<0, true>(A, B, bias, nullptr, C, 512, 512, blockIdx.y*64, bn, smem);
}

// ---------------- fused fp16 attention per (b,h) (R14 proven) --------------
#define ATTN_SMEM ((64*72 + 128*36 + 128*36)*4)   // 55296 B
__global__ void __launch_bounds__(256) attn_kernel() {
    extern __shared__ uint32_t smw[];
    uint32_t* Vs = smw;
    uint32_t* Qs = smw + 64*72;
    uint32_t* Ks = Qs + 128*36;
    uint32_t* Ps = Qs;   // [128][68]

    int bh = blockIdx.x, b = bh >> 3, h = bh & 7;
    int tid = threadIdx.x, warp = tid>>5, lane = tid&31;
    int lr = lane>>2, lc = lane&3;
    const uint32_t* qp = g_qh + (size_t)(b*SEQL)*256 + h*32;
    const uint32_t* kp = g_kh + (size_t)(b*SEQL)*256 + h*32;
    const uint32_t* vp = g_vh + (size_t)(b*SEQL)*256 + h*32;

    #pragma unroll
    for (int i = 0; i < 4; i++) {
        int idx = tid + i*256;
        int s = idx >> 3, pos = (idx & 7)*4;
        *(uint4*)&Qs[s*36 + pos] = *(const uint4*)(qp + (size_t)s*256 + pos);
        *(uint4*)&Ks[s*36 + pos] = *(const uint4*)(kp + (size_t)s*256 + pos);
    }
    #pragma unroll
    for (int i = 0; i < 8; i++) {
        int t = tid + i*256;
        int sp = t >> 5, dp = t & 31;
        uint32_t w0 = vp[(size_t)(2*sp)*256 + dp];
        uint32_t w1 = vp[(size_t)(2*sp+1)*256 + dp];
        Vs[sp*72 + 2*dp]     = __byte_perm(w0, w1, 0x5410);
        Vs[sp*72 + 2*dp + 1] = __byte_perm(w0, w1, 0x7632);
    }
    __syncthreads();

    int qr = warp*16 + lr;
    float accs[16][4] = {};
    #pragma unroll
    for (int st = 0; st < 4; st++) {
        int cw = st*8 + lc;
        uint32_t a0 = Qs[qr*36 + cw],     a1 = Qs[(qr+8)*36 + cw];
        uint32_t a2 = Qs[qr*36 + cw + 4], a3 = Qs[(qr+8)*36 + cw + 4];
        #pragma unroll
        for (int nt = 0; nt < 16; nt++) {
            int kn = nt*8 + lr;
            uint32_t b0 = Ks[kn*36 + cw];
            uint32_t b1 = Ks[kn*36 + cw + 4];
            mma_f16(accs[nt], a0, a1, a2, a3, b0, b1);
        }
    }
    float m0 = -1e30f, m1 = -1e30f;
    #pragma unroll
    for (int nt = 0; nt < 16; nt++) {
        #pragma unroll
        for (int j = 0; j < 4; j++) accs[nt][j] *= 0.125f;
        m0 = fmaxf(m0, fmaxf(accs[nt][0], accs[nt][1]));
        m1 = fmaxf(m1, fmaxf(accs[nt][2], accs[nt][3]));
    }
    m0 = fmaxf(m0, __shfl_xor_sync(0xffffffffu, m0, 1));
    m0 = fmaxf(m0, __shfl_xor_sync(0xffffffffu, m0, 2));
    m1 = fmaxf(m1, __shfl_xor_sync(0xffffffffu, m1, 1));
    m1 = fmaxf(m1, __shfl_xor_sync(0xffffffffu, m1, 2));
    float s0 = 0.f, s1 = 0.f;
    #pragma unroll
    for (int nt = 0; nt < 16; nt++) {
        accs[nt][0] = __expf(accs[nt][0] - m0);
        accs[nt][1] = __expf(accs[nt][1] - m0);
        accs[nt][2] = __expf(accs[nt][2] - m1);
        accs[nt][3] = __expf(accs[nt][3] - m1);
        s0 += accs[nt][0] + accs[nt][1];
        s1 += accs[nt][2] + accs[nt][3];
    }
    s0 += __shfl_xor_sync(0xffffffffu, s0, 1);
    s0 += __shfl_xor_sync(0xffffffffu, s0, 2);
    s1 += __shfl_xor_sync(0xffffffffu, s1, 1);
    s1 += __shfl_xor_sync(0xffffffffu, s1, 2);
    float i0 = 1.f/s0, i1 = 1.f/s1;

    __syncthreads();
    #pragma unroll
    for (int nt = 0; nt < 16; nt++) {
        int wdi = nt*4 + lc;
        Ps[qr*68 + wdi]     = pkh2(accs[nt][0]*i0, accs[nt][1]*i0);
        Ps[(qr+8)*68 + wdi] = pkh2(accs[nt][2]*i1, accs[nt][3]*i1);
    }
    __syncthreads();

    float acco[8][4] = {};
    #pragma unroll
    for (int kk = 0; kk < 8; kk++) {
        int cw = kk*8 + lc;
        uint32_t a0 = Ps[qr*68 + cw],     a1 = Ps[(qr+8)*68 + cw];
        uint32_t a2 = Ps[qr*68 + cw + 4], a3 = Ps[(qr+8)*68 + cw + 4];
        #pragma unroll
        for (int nt = 0; nt < 8; nt++) {
            int dn = nt*8 + lr;
            uint32_t b0 = Vs[cw*72 + dn];
            uint32_t b1 = Vs[(cw+4)*72 + dn];
            mma_f16(acco[nt], a0, a1, a2, a3, b0, b1);
        }
    }
    uint32_t* op = g_oh + (size_t)(b*SEQL)*256 + h*32;
    #pragma unroll
    for (int nt = 0; nt < 8; nt++) {
        int wdi = nt*4 + lc;
        op[(size_t)qr*256 + wdi]     = pkh2(acco[nt][0], acco[nt][1]);
        op[(size_t)(qr+8)*256 + wdi] = pkh2(acco[nt][2], acco[nt][3]);
    }
}

// ---------------- bilinear upsample 8x8 -> 32x32, 8-d blocks ---------------
__global__ void upsample_kernel(float* __restrict__ out) {
    __shared__ float g[8][65];
    int d0 = blockIdx.x*8, b = blockIdx.y, which = blockIdx.z;
    int tid = threadIdx.x;
    {
        int s = tid >> 3, dl = tid & 7;
        #pragma unroll
        for (int i = 0; i < 2; i++) {
            int ss = s + i*32;
            g[dl][ss] = g_ln[(size_t)(b*SEQL + which*64 + ss)*512 + d0 + dl];
        }
    }
    __syncthreads();
    int dl = tid >> 5, lane = tid & 31;
    float* op = out + (size_t)which*(BSZ*512*1024)
                    + ((size_t)(b*512 + d0 + dl))*1024;
    const float* gr = g[dl];
    #pragma unroll
    for (int r = 0; r < 32; r++) {
        int pix = lane + r*32;
        int oy = pix >> 5, ox = pix & 31;
        float cy = (oy + 0.5f)*0.25f - 0.5f;
        float cx = (ox + 0.5f)*0.25f - 0.5f;
        int y0 = (int)floorf(cy); float wy = cy - y0;
        int x0 = (int)floorf(cx); float wx = cx - x0;
        int y1 = min(y0+1, 7); y0 = max(y0, 0);
        int x1 = min(x0+1, 7); x0 = max(x0, 0);
        float v00 = gr[y0*8+x0], v01 = gr[y0*8+x1], v10 = gr[y1*8+x0], v11 = gr[y1*8+x1];
        op[pix] = (1.f-wy)*((1.f-wx)*v00 + wx*v01) + wy*((1.f-wx)*v10 + wx*v11);
    }
}

// ---------------- launcher --------------------------------------------------
extern "C" void kernel_launch(void* const* d_in, const int* in_sizes, int n_in,
                              void* d_out, int out_size) {
    const float* rgb  = (const float*)d_in[0];
    const float* ir   = (const float*)d_in[1];
    const float* pos  = (const float*)d_in[2];
    const float* c1w  = (const float*)d_in[3];
    const float* c2w  = (const float*)d_in[4];
    const float* ln1w = (const float*)d_in[5];
    const float* ln1b = (const float*)d_in[6];
    const float* Wq   = (const float*)d_in[7];
    const float* bq   = (const float*)d_in[8];
    const float* Wk   = (const float*)d_in[9];
    const float* bk   = (const float*)d_in[10];
    const float* Wv   = (const float*)d_in[11];
    const float* bv   = (const float*)d_in[12];
    const float* Wo   = (const float*)d_in[13];
    const float* bo   = (const float*)d_in[14];
    const float* ln2w = (const float*)d_in[15];
    const float* ln2b = (const float*)d_in[16];
    const float* W1   = (const float*)d_in[17];
    const float* b1   = (const float*)d_in[18];
    const float* W2   = (const float*)d_in[19];
    const float* b2   = (const float*)d_in[20];
    const float* lnfw = (const float*)d_in[21];
    const float* lnfb = (const float*)d_in[22];
    float* out = (float*)d_out;

    float *p_x, *p_ln;
    uint32_t *p_lnh, *p_qh, *p_kh, *p_vh, *p_oh, *p_hh;
    uint32_t *p_wq, *p_wk, *p_wv, *p_wo, *p_w1, *p_w2;
    cudaGetSymbolAddress((void**)&p_x,   g_x);
    cudaGetSymbolAddress((void**)&p_ln,  g_ln);
    cudaGetSymbolAddress((void**)&p_lnh, g_lnh);
    cudaGetSymbolAddress((void**)&p_qh,  g_qh);
    cudaGetSymbolAddress((void**)&p_kh,  g_kh);
    cudaGetSymbolAddress((void**)&p_vh,  g_vh);
    cudaGetSymbolAddress((void**)&p_oh,  g_oh);
    cudaGetSymbolAddress((void**)&p_hh,  g_hh);
    cudaGetSymbolAddress((void**)&p_wq,  g_wq);
    cudaGetSymbolAddress((void**)&p_wk,  g_wk);
    cudaGetSymbolAddress((void**)&p_wv,  g_wv);
    cudaGetSymbolAddress((void**)&p_wo,  g_wo);
    cudaGetSymbolAddress((void**)&p_w1,  g_w1);
    cudaGetSymbolAddress((void**)&p_w2,  g_w2);

    cudaFuncSetAttribute(attn_kernel, cudaFuncAttributeMaxDynamicSharedMemorySize, ATTN_SMEM);
    cudaFuncSetAttribute(gemm_qkv_kernel, cudaFuncAttributeMaxDynamicSharedMemorySize, GEMM_SMEM);
    cudaFuncSetAttribute(gemm_kernel<2,false>, cudaFuncAttributeMaxDynamicSharedMemorySize, GEMM_SMEM);
    cudaFuncSetAttribute(gemm_kernel<1,true>, cudaFuncAttributeMaxDynamicSharedMemorySize, GEMM_SMEM);

    pack_all<<<(PACK_TOTAL+255)/256, 256>>>(Wq, Wk, Wv, Wo, W1, W2,
                                            p_wq, p_wk, p_wv, p_wo, p_w1, p_w2);

    pool_hp_kernel<<<dim3(DMODEL, BSZ, 2), 256>>>(rgb, ir);
    conv1_kernel<<<dim3(BSZ, 4), 512>>>(c1w);
    loss_partA<<<36, 256>>>();
    loss_partB<<<1, 64>>>(out + (size_t)2*BSZ*512*1024);
    buildx_kernel<<<dim3(4, BSZ, 2), 512>>>(pos, c2w);

    dim3 gqkv(12, NTOK/64);          // 768 CTAs
    dim3 g512(4, NTOK/64);           // 256 CTAs
    dim3 g2048(16, NTOK/64);         // 1024 CTAs

    for (int l = 0; l < NLAYER; l++) {
        size_t wOff = (size_t)l*(DMODEL/2)*DMODEL;
        size_t w1Off = (size_t)l*(DMODEL/2)*HID;
        size_t w2Off = (size_t)l*(HID/2)*DMODEL;
        size_t bOff = (size_t)l*512, b1Off = (size_t)l*2048;
        ln_kernel<true><<<NTOK/8, 256>>>(p_x, p_lnh, ln1w + bOff, ln1b + bOff);
        gemm_qkv_kernel<<<gqkv, 128, GEMM_SMEM>>>(p_lnh,
            p_wq + wOff, p_wk + wOff, p_wv + wOff,
            bq + bOff, bk + bOff, bv + bOff, p_qh, p_kh, p_vh);
        attn_kernel<<<BSZ*NHEAD, 256, ATTN_SMEM>>>();
        gemm_kernel<2,false><<<g512, 128, GEMM_SMEM>>>(p_oh, p_wo + wOff,
            bo + bOff, p_x, p_x, 512, 512);
        ln_kernel<true><<<NTOK/8, 256>>>(p_x, p_lnh, ln2w + bOff, ln2b + bOff);
        gemm_kernel<1,true><<<g2048, 128, GEMM_SMEM>>>(p_lnh, p_w1 + w1Off,
            b1 + b1Off, nullptr, p_hh, 2048, 512);
        gemm_kernel<2,false><<<g512, 128, GEMM_SMEM>>>(p_hh, p_w2 + w2Off,
            b2 + bOff, p_x, p_x, 512, 2048);
    }
    ln_kernel<false><<<NTOK/8, 256>>>(p_x, p_ln, lnfw, lnfb);
    upsample_kernel<<<dim3(64, BSZ, 2), 256>>>(out);
}